// round 10
// baseline (speedup 1.0000x reference)
#include <cuda_runtime.h>
#include <cuda_fp16.h>
#include <cstdint>
#include <math.h>

#define NB 16
#define NC 256

// ---------------- scratch (device globals: no allocs allowed) ----------------
__device__ __half g_D1[NB*NC*4096];
__device__ __half g_D2[NB*NC*2048];
__device__ __half g_D3[NB*NC*1024];
__device__ __half g_A3[NB*NC*1024];
__device__ __half g_S [NB*NC*8192];
__device__ __half g_Wh[4*NC*NC];    // fp16 weights: ab_w1, ab_w2, db_w1, db_w2

// ---------------- db4 filters ----------------
__constant__ float c_dec_lo[8] = {-0.010597401785069032f, 0.0328830116668852f, 0.030841381835560764f, -0.18703481171888114f, -0.027983769416859854f, 0.6308807679298589f, 0.7148465705529157f, 0.2303778133088965f};
__constant__ float c_dec_hi[8] = {-0.2303778133088965f, 0.7148465705529157f, -0.6308807679298589f, -0.027983769416859854f, 0.18703481171888114f, 0.030841381835560764f, -0.0328830116668852f, -0.010597401785069032f};
__constant__ float c_rec_lo[8] = {0.2303778133088965f, 0.7148465705529157f, 0.6308807679298589f, -0.027983769416859854f, -0.18703481171888114f, 0.030841381835560764f, 0.0328830116668852f, -0.010597401785069032f};
__constant__ float c_rec_hi[8] = {-0.010597401785069032f, -0.0328830116668852f, 0.030841381835560764f, 0.18703481171888114f, -0.027983769416859854f, -0.6308807679298589f, 0.7148465705529157f, -0.2303778133088965f};

// ================= helpers =================
__device__ __forceinline__ uint32_t smem_u32(const void* p) {
    uint32_t a;
    asm("{ .reg .u64 t; cvta.to.shared.u64 t, %1; cvt.u32.u64 %0, t; }" : "=r"(a) : "l"(p));
    return a;
}
__device__ __forceinline__ void cp16(uint32_t dst, const void* src) {
    asm volatile("cp.async.cg.shared.global [%0], [%1], 16;" :: "r"(dst), "l"(src));
}
__device__ __forceinline__ void cp_commit() { asm volatile("cp.async.commit_group;" ::: "memory"); }
__device__ __forceinline__ void cp_wait2()  { asm volatile("cp.async.wait_group 2;" ::: "memory"); }

__device__ __forceinline__ void mma_f16(float* c, const uint32_t* a, const uint32_t* b) {
    asm volatile("mma.sync.aligned.m16n8k16.row.col.f32.f16.f16.f32 "
                 "{%0,%1,%2,%3}, {%4,%5,%6,%7}, {%8,%9}, {%0,%1,%2,%3};"
                 : "+f"(c[0]), "+f"(c[1]), "+f"(c[2]), "+f"(c[3])
                 : "r"(a[0]), "r"(a[1]), "r"(a[2]), "r"(a[3]), "r"(b[0]), "r"(b[1]));
}
__device__ __forceinline__ void ldsm4(uint32_t* r, uint32_t addr) {
    asm volatile("ldmatrix.sync.aligned.m8n8.x4.shared.b16 {%0,%1,%2,%3}, [%4];"
                 : "=r"(r[0]), "=r"(r[1]), "=r"(r[2]), "=r"(r[3]) : "r"(addr));
}
__device__ __forceinline__ void ldsm4t(uint32_t* r, uint32_t addr) {
    asm volatile("ldmatrix.sync.aligned.m8n8.x4.trans.shared.b16 {%0,%1,%2,%3}, [%4];"
                 : "=r"(r[0]), "=r"(r[1]), "=r"(r[2]), "=r"(r[3]) : "r"(addr));
}
__device__ __forceinline__ float gelu_tanh(float x) {
    const float k0 = 0.7978845608028654f;
    const float k1 = 0.044715f;
    float x3 = x * x * x;
    float t = tanhf(k0 * (x + k1 * x3));
    return 0.5f * x * (1.f + t);
}

// ---------------- convert weights to fp16 ----------------
__global__ __launch_bounds__(256) void convw_kernel(const float* __restrict__ w0,
                                                    const float* __restrict__ w1,
                                                    const float* __restrict__ w2,
                                                    const float* __restrict__ w3,
                                                    __half* __restrict__ out) {
    int i = blockIdx.x * 256 + threadIdx.x;
    const float* src[4] = {w0, w1, w2, w3};
#pragma unroll
    for (int m = 0; m < 4; m++) {
        float4 v = *(const float4*)(src[m] + i * 4);
        __half2 h0 = __floats2half2_rn(v.x, v.y);
        __half2 h1 = __floats2half2_rn(v.z, v.w);
        uint2 pk = make_uint2(*(uint32_t*)&h0, *(uint32_t*)&h1);
        *(uint2*)(out + m * 65536 + i * 4) = pk;
    }
}

// ================= fused 3-level DWT (even/odd smem split, pair-processed) =================
#define DWT_SMEM_F (2*4104 + 2*2056 + 2*1032)

__device__ __forceinline__ void dwt_level_h(const float* __restrict__ E, const float* __restrict__ O,
                                            int Lh, __half* __restrict__ dOut,
                                            float* EO, float* OO, __half* aOut) {
    for (int i = threadIdx.x; i < (Lh >> 1); i += 512) {
        int j = 2 * i;
        const float* e = E + 4 + j;
        const float* o = O + 4 + j;
        float em1 = e[-1], e0 = e[0], e1 = e[1], e2 = e[2], e3 = e[3];
        float om2 = o[-2], om1 = o[-1], o0 = o[0], o1 = o[1], o2 = o[2];
        float a0 = em1*c_dec_lo[1] + e0*c_dec_lo[3] + e1*c_dec_lo[5] + e2*c_dec_lo[7]
                 + om2*c_dec_lo[0] + om1*c_dec_lo[2] + o0*c_dec_lo[4] + o1*c_dec_lo[6];
        float a1 = e0*c_dec_lo[1] + e1*c_dec_lo[3] + e2*c_dec_lo[5] + e3*c_dec_lo[7]
                 + om1*c_dec_lo[0] + o0*c_dec_lo[2] + o1*c_dec_lo[4] + o2*c_dec_lo[6];
        float d0 = em1*c_dec_hi[1] + e0*c_dec_hi[3] + e1*c_dec_hi[5] + e2*c_dec_hi[7]
                 + om2*c_dec_hi[0] + om1*c_dec_hi[2] + o0*c_dec_hi[4] + o1*c_dec_hi[6];
        float d1 = e0*c_dec_hi[1] + e1*c_dec_hi[3] + e2*c_dec_hi[5] + e3*c_dec_hi[7]
                 + om1*c_dec_hi[0] + o0*c_dec_hi[2] + o1*c_dec_hi[4] + o2*c_dec_hi[6];
        *(__half2*)&dOut[j] = __floats2half2_rn(d0, d1);
        if (aOut) *(__half2*)&aOut[j] = __floats2half2_rn(a0, a1);
        else { EO[4 + i] = a0; OO[4 + i] = a1; }
    }
}

__global__ __launch_bounds__(512) void fused_dwt(const float* __restrict__ x,
                                                 __half* __restrict__ D1,
                                                 __half* __restrict__ D2,
                                                 __half* __restrict__ D3,
                                                 __half* __restrict__ A3) {
    extern __shared__ float sm[];
    float* E1 = sm;            // 4104
    float* O1 = sm + 4104;
    float* E2 = sm + 8208;     // 2056
    float* O2 = sm + 10264;
    float* E3 = sm + 12320;    // 1032
    float* O3 = sm + 13352;
    int row = blockIdx.x, tid = threadIdx.x;

    if (tid < 48) {            // zero pads
        int a = tid >> 3, p = tid & 7;
        float* bases[6] = {E1, O1, E2, O2, E3, O3};
        int lens[6] = {4096, 4096, 2048, 2048, 1024, 1024};
        bases[a][p < 4 ? p : lens[a] + p] = 0.f;
    }
    const float4* x4 = (const float4*)(x + (size_t)row * 8192);
    for (int i = tid; i < 2048; i += 512) {
        float4 v = x4[i];
        *(float2*)&E1[4 + 2*i] = make_float2(v.x, v.z);
        *(float2*)&O1[4 + 2*i] = make_float2(v.y, v.w);
    }
    __syncthreads();
    dwt_level_h(E1, O1, 4096, D1 + (size_t)row * 4096, E2, O2, nullptr);
    __syncthreads();
    dwt_level_h(E2, O2, 2048, D2 + (size_t)row * 2048, E3, O3, nullptr);
    __syncthreads();
    dwt_level_h(E3, O3, 1024, D3 + (size_t)row * 1024, nullptr, nullptr, A3 + (size_t)row * 1024);
}

// ================= fused 3-level IDWT + skip, quad-processed, conflict-free =================
#define IDWT_A3H 0
#define IDWT_D3H 2080
#define IDWT_D2H 4160
#define IDWT_D1H 8288
#define IDWT_Y2  16512
#define IDWT_Y1  24736
#define IDWT_SMEM_B 41152

__global__ __launch_bounds__(512) void fused_idwt(const __half* __restrict__ A3v,
                                                  const __half* __restrict__ D3v,
                                                  const __half* __restrict__ D2v,
                                                  const __half* __restrict__ D1v,
                                                  const float* __restrict__ x,
                                                  __half* __restrict__ S) {
    extern __shared__ char smc[];
    __half* A3h = (__half*)(smc + IDWT_A3H);
    __half* D3h = (__half*)(smc + IDWT_D3H);
    __half* D2h = (__half*)(smc + IDWT_D2H);
    __half* D1h = (__half*)(smc + IDWT_D1H);
    float*  Y2  = (float*)(smc + IDWT_Y2);
    float*  Y1  = (float*)(smc + IDWT_Y1);
    int row = blockIdx.x, tid = threadIdx.x;

    if (tid < 8) {
        __half* hb[4] = {A3h, D3h, D2h, D1h};
        int hl[4] = {1024, 1024, 2048, 4096};
        int a = tid >> 1, e = tid & 1;
        uint4 z = make_uint4(0, 0, 0, 0);
        *(uint4*)&hb[a][e ? 8 + hl[a] : 0] = z;
    } else if (tid < 12) {
        float* fb[2] = {Y2, Y1};
        int fl[2] = {2048, 4096};
        int a = (tid - 8) >> 1, e = tid & 1;
        *(float4*)&fb[a][e ? 4 + fl[a] : 0] = make_float4(0.f, 0.f, 0.f, 0.f);
    }
    {
        const uint4* a3 = (const uint4*)(A3v + (size_t)row * 1024);
        const uint4* d3 = (const uint4*)(D3v + (size_t)row * 1024);
        const uint4* d2 = (const uint4*)(D2v + (size_t)row * 2048);
        const uint4* d1 = (const uint4*)(D1v + (size_t)row * 4096);
        if (tid < 128)       *(uint4*)&A3h[8 + 8 * tid] = a3[tid];
        else if (tid < 256)  *(uint4*)&D3h[8 + 8 * (tid - 128)] = d3[tid - 128];
        else                 *(uint4*)&D2h[8 + 8 * (tid - 256)] = d2[tid - 256];
        *(uint4*)&D1h[8 + 8 * tid] = d1[tid];
    }
    __syncthreads();

    {
        int i = tid;
        float2 am = __half22float2(*(const __half2*)&A3h[6 + 2*i]);
        float2 ac = __half22float2(*(const __half2*)&A3h[8 + 2*i]);
        float2 ap = __half22float2(*(const __half2*)&A3h[10 + 2*i]);
        float2 dm = __half22float2(*(const __half2*)&D3h[6 + 2*i]);
        float2 dc = __half22float2(*(const __half2*)&D3h[8 + 2*i]);
        float2 dp = __half22float2(*(const __half2*)&D3h[10 + 2*i]);
        float y0 = am.x*c_rec_lo[7] + am.y*c_rec_lo[5] + ac.x*c_rec_lo[3] + ac.y*c_rec_lo[1]
                 + dm.x*c_rec_hi[7] + dm.y*c_rec_hi[5] + dc.x*c_rec_hi[3] + dc.y*c_rec_hi[1];
        float y1 = am.y*c_rec_lo[6] + ac.x*c_rec_lo[4] + ac.y*c_rec_lo[2] + ap.x*c_rec_lo[0]
                 + dm.y*c_rec_hi[6] + dc.x*c_rec_hi[4] + dc.y*c_rec_hi[2] + dp.x*c_rec_hi[0];
        float y2 = am.y*c_rec_lo[7] + ac.x*c_rec_lo[5] + ac.y*c_rec_lo[3] + ap.x*c_rec_lo[1]
                 + dm.y*c_rec_hi[7] + dc.x*c_rec_hi[5] + dc.y*c_rec_hi[3] + dp.x*c_rec_hi[1];
        float y3 = ac.x*c_rec_lo[6] + ac.y*c_rec_lo[4] + ap.x*c_rec_lo[2] + ap.y*c_rec_lo[0]
                 + dc.x*c_rec_hi[6] + dc.y*c_rec_hi[4] + dp.x*c_rec_hi[2] + dp.y*c_rec_hi[0];
        *(float4*)&Y2[4 + 4*i] = make_float4(y0, y1, y2, y3);
    }
    __syncthreads();

#pragma unroll
    for (int q = 0; q < 2; q++) {
        int i = tid + q * 512;
        float2 am = *(const float2*)&Y2[2 + 2*i];
        float2 ac = *(const float2*)&Y2[4 + 2*i];
        float2 ap = *(const float2*)&Y2[6 + 2*i];
        float2 dm = __half22float2(*(const __half2*)&D2h[6 + 2*i]);
        float2 dc = __half22float2(*(const __half2*)&D2h[8 + 2*i]);
        float2 dp = __half22float2(*(const __half2*)&D2h[10 + 2*i]);
        float y0 = am.x*c_rec_lo[7] + am.y*c_rec_lo[5] + ac.x*c_rec_lo[3] + ac.y*c_rec_lo[1]
                 + dm.x*c_rec_hi[7] + dm.y*c_rec_hi[5] + dc.x*c_rec_hi[3] + dc.y*c_rec_hi[1];
        float y1 = am.y*c_rec_lo[6] + ac.x*c_rec_lo[4] + ac.y*c_rec_lo[2] + ap.x*c_rec_lo[0]
                 + dm.y*c_rec_hi[6] + dc.x*c_rec_hi[4] + dc.y*c_rec_hi[2] + dp.x*c_rec_hi[0];
        float y2 = am.y*c_rec_lo[7] + ac.x*c_rec_lo[5] + ac.y*c_rec_lo[3] + ap.x*c_rec_lo[1]
                 + dm.y*c_rec_hi[7] + dc.x*c_rec_hi[5] + dc.y*c_rec_hi[3] + dp.x*c_rec_hi[1];
        float y3 = ac.x*c_rec_lo[6] + ac.y*c_rec_lo[4] + ap.x*c_rec_lo[2] + ap.y*c_rec_lo[0]
                 + dc.x*c_rec_hi[6] + dc.y*c_rec_hi[4] + dp.x*c_rec_hi[2] + dp.y*c_rec_hi[0];
        *(float4*)&Y1[4 + 4*i] = make_float4(y0, y1, y2, y3);
    }
    __syncthreads();

    const float* xr = x + (size_t)row * 8192;
    __half* Sr = S + (size_t)row * 8192;
#pragma unroll
    for (int q = 0; q < 4; q++) {
        int i = tid + q * 512;
        float2 am = *(const float2*)&Y1[2 + 2*i];
        float2 ac = *(const float2*)&Y1[4 + 2*i];
        float2 ap = *(const float2*)&Y1[6 + 2*i];
        float2 dm = __half22float2(*(const __half2*)&D1h[6 + 2*i]);
        float2 dc = __half22float2(*(const __half2*)&D1h[8 + 2*i]);
        float2 dp = __half22float2(*(const __half2*)&D1h[10 + 2*i]);
        float y0 = am.x*c_rec_lo[7] + am.y*c_rec_lo[5] + ac.x*c_rec_lo[3] + ac.y*c_rec_lo[1]
                 + dm.x*c_rec_hi[7] + dm.y*c_rec_hi[5] + dc.x*c_rec_hi[3] + dc.y*c_rec_hi[1];
        float y1 = am.y*c_rec_lo[6] + ac.x*c_rec_lo[4] + ac.y*c_rec_lo[2] + ap.x*c_rec_lo[0]
                 + dm.y*c_rec_hi[6] + dc.x*c_rec_hi[4] + dc.y*c_rec_hi[2] + dp.x*c_rec_hi[0];
        float y2 = am.y*c_rec_lo[7] + ac.x*c_rec_lo[5] + ac.y*c_rec_lo[3] + ap.x*c_rec_lo[1]
                 + dm.y*c_rec_hi[7] + dc.x*c_rec_hi[5] + dc.y*c_rec_hi[3] + dp.x*c_rec_hi[1];
        float y3 = ac.x*c_rec_lo[6] + ac.y*c_rec_lo[4] + ap.x*c_rec_lo[2] + ap.y*c_rec_lo[0]
                 + dc.x*c_rec_hi[6] + dc.y*c_rec_hi[4] + dp.x*c_rec_hi[2] + dp.y*c_rec_hi[0];
        float4 xv = *(const float4*)&xr[4*i];
        __half2 h0 = __floats2half2_rn(y0 + xv.x, y1 + xv.y);
        __half2 h1 = __floats2half2_rn(y2 + xv.z, y3 + xv.w);
        uint2 pk = make_uint2(*(uint32_t*)&h0, *(uint32_t*)&h1);
        *(uint2*)&Sr[4*i] = pk;
    }
}

// ================= combined fused res blocks, B fully prefetched =================
// A: 4-stage ring (L2-hot weights). B: all 8 chunks issued in prologue group 0
// (70KB in flight -> DRAM latency fully hidden); X stays resident for epilogue.
#define A_STAGE_B (256*80)      // 20480
#define B_STAGE_B (32*272)      // 8704
#define H_BYTES   (256*272)     // 69632
#define RS_SMEM   (4*A_STAGE_B + 8*B_STAGE_B + H_BYTES)   // 221184

__global__ __launch_bounds__(512, 1) void resblock_all(
        __half* __restrict__ D3, __half* __restrict__ A3,
        __half* __restrict__ D2, __half* __restrict__ D1,
        const __half* __restrict__ Wh,
        const float* __restrict__ ab_b1, const float* __restrict__ ab_b2,
        const float* __restrict__ db_b1, const float* __restrict__ db_b2) {
    extern __shared__ char smem[];
    uint32_t sA = smem_u32(smem);
    uint32_t sB = sA + 4 * A_STAGE_B;
    uint32_t sH = sB + 8 * B_STAGE_B;

    int tid = threadIdx.x;
    int wid = tid >> 5, lane = tid & 31;
    int wm = wid >> 2, wn = wid & 3;
    int g = lane >> 2, tt = lane & 3;
    int l15 = lane & 15, lhi = (lane >> 4) << 4;

    int id = blockIdx.x;
    int b = id >> 6, slot = id & 63;
    __half* X; int L, ln;
    const __half *W1, *W2; const float *b1, *b2;
    if (slot < 8)       { X = D3; L = 1024; ln = slot * 128;        W1 = Wh + 2*65536; W2 = Wh + 3*65536; b1 = db_b1; b2 = db_b2; }
    else if (slot < 16) { X = A3; L = 1024; ln = (slot - 8) * 128;  W1 = Wh + 0*65536; W2 = Wh + 1*65536; b1 = ab_b1; b2 = ab_b2; }
    else if (slot < 32) { X = D2; L = 2048; ln = (slot - 16) * 128; W1 = Wh + 2*65536; W2 = Wh + 3*65536; b1 = db_b1; b2 = db_b2; }
    else                { X = D1; L = 4096; ln = (slot - 32) * 128; W1 = Wh + 2*65536; W2 = Wh + 3*65536; b1 = db_b1; b2 = db_b2; }
    __half* Xb = X + (size_t)b * NC * L + ln;

    float acc[4][4][4];
#pragma unroll
    for (int mt = 0; mt < 4; mt++)
#pragma unroll
        for (int nt = 0; nt < 4; nt++)
#pragma unroll
            for (int r = 0; r < 4; r++) acc[mt][nt][r] = 0.f;

    auto loadA = [&](int c, int s) {
        const __half* wsrc = (c < 8 ? W1 : W2) + (c & 7) * 32;
#pragma unroll
        for (int q = 0; q < 2; q++) {
            int idx = tid + q * 512;
            int r = idx >> 2, u = idx & 3;
            cp16(sA + s * A_STAGE_B + r * 80 + u * 16, wsrc + r * 256 + u * 8);
        }
    };
    auto loadB = [&](int c) {
        int k = tid >> 4, u = tid & 15;
        cp16(sB + c * B_STAGE_B + k * 272 + u * 16,
             Xb + (size_t)(c * 32 + k) * L + u * 8);
    };
    auto compute = [&](int c, int s) {
        uint32_t Abase = sA + s * A_STAGE_B + (wm * 64) * 80;
        uint32_t Bbase = (c < 8) ? (sB + (uint32_t)c * B_STAGE_B)
                                 : (sH + (uint32_t)(c - 8) * 32 * 272);
#pragma unroll
        for (int kk = 0; kk < 2; kk++) {
            uint32_t a[4][4];
#pragma unroll
            for (int mt = 0; mt < 4; mt++)
                ldsm4(a[mt], Abase + (mt * 16 + l15) * 80 + kk * 32 + lhi);
            uint32_t bf[2][4];
#pragma unroll
            for (int p = 0; p < 2; p++)
                ldsm4t(bf[p], Bbase + (kk * 16 + l15) * 272 + (wn * 32 + p * 16) * 2 + lhi);
#pragma unroll
            for (int mt = 0; mt < 4; mt++)
#pragma unroll
                for (int nt = 0; nt < 4; nt++)
                    mma_f16(acc[mt][nt], a[mt], &bf[nt >> 1][(nt & 1) * 2]);
        }
    };

    // prologue: ALL B chunks + A0 in group 0; A1, A2 as groups 1, 2
#pragma unroll
    for (int c = 0; c < 8; c++) loadB(c);
    loadA(0, 0); cp_commit();
    loadA(1, 1); cp_commit();
    loadA(2, 2); cp_commit();

#pragma unroll 1
    for (int c = 0; c < 16; c++) {
        int s = c & 3;
        cp_wait2();
        __syncthreads();
        if (c + 3 < 16) loadA(c + 3, (c + 3) & 3);
        cp_commit();
        compute(c, s);
        if (c == 7) {
#pragma unroll
            for (int mt = 0; mt < 4; mt++)
#pragma unroll
                for (int hh = 0; hh < 2; hh++) {
                    int m = wm * 64 + mt * 16 + g + hh * 8;
                    float bb = b1[m];
#pragma unroll
                    for (int nt = 0; nt < 4; nt++) {
                        float v0 = gelu_tanh(acc[mt][nt][hh * 2 + 0] + bb);
                        float v1 = gelu_tanh(acc[mt][nt][hh * 2 + 1] + bb);
                        __half2 h = __floats2half2_rn(v0, v1);
                        asm volatile("st.shared.b32 [%0], %1;"
                                     :: "r"(sH + m * 272 + (wn * 32 + nt * 8 + tt * 2) * 2),
                                        "r"(*(uint32_t*)&h));
                        acc[mt][nt][hh * 2 + 0] = 0.f;
                        acc[mt][nt][hh * 2 + 1] = 0.f;
                    }
                }
        }
    }

    // ---- epilogue: X(gmem) = X(smem-resident) + acc + b2 ----
#pragma unroll
    for (int mt = 0; mt < 4; mt++)
#pragma unroll
        for (int hh = 0; hh < 2; hh++) {
            int m = wm * 64 + mt * 16 + g + hh * 8;
            float bb = b2[m];
            size_t orow = (size_t)m * L;
            uint32_t xrow = sB + (uint32_t)(m >> 5) * B_STAGE_B + (uint32_t)(m & 31) * 272;
#pragma unroll
            for (int nt = 0; nt < 4; nt++) {
                int col = wn * 32 + nt * 8 + tt * 2;
                uint32_t xv;
                asm volatile("ld.shared.b32 %0, [%1];" : "=r"(xv) : "r"(xrow + col * 2));
                float2 rr = __half22float2(*(__half2*)&xv);
                float v0 = acc[mt][nt][hh * 2 + 0] + bb + rr.x;
                float v1 = acc[mt][nt][hh * 2 + 1] + bb + rr.y;
                *(__half2*)&Xb[orow + col] = __floats2half2_rn(v0, v1);
            }
        }
}

// ---------------- LayerNorm over channels: fp16 in, fp32 out ----------------
__global__ __launch_bounds__(256) void ln_kernel(const __half* __restrict__ S,
                                                 const float* __restrict__ g,
                                                 const float* __restrict__ bt,
                                                 float* __restrict__ out) {
    int b = blockIdx.y;
    int l0 = blockIdx.x * 128;
    int tx = threadIdx.x & 63;
    int ty = threadIdx.x >> 6;
    const __half2* Sb = (const __half2*)S;
    uint32_t r[64];
    float s0 = 0.f, s1 = 0.f, q0 = 0.f, q1 = 0.f;
#pragma unroll
    for (int q = 0; q < 64; q++) {
        int c = ty + 4 * q;
        __half2 h = Sb[(size_t)(b * NC + c) * 4096 + (l0 >> 1) + tx];
        r[q] = *(uint32_t*)&h;
        float2 f = __half22float2(h);
        s0 += f.x; s1 += f.y;
        q0 = fmaf(f.x, f.x, q0);
        q1 = fmaf(f.y, f.y, q1);
    }
    __shared__ float2 ssum[4][64], ssq[4][64];
    __shared__ float2 smu[64], srs[64];
    ssum[ty][tx] = make_float2(s0, s1);
    ssq[ty][tx] = make_float2(q0, q1);
    __syncthreads();
    if (ty == 0) {
        float2 s = ssum[0][tx], q = ssq[0][tx];
#pragma unroll
        for (int t = 1; t < 4; t++) {
            s.x += ssum[t][tx].x; s.y += ssum[t][tx].y;
            q.x += ssq[t][tx].x;  q.y += ssq[t][tx].y;
        }
        float mu0 = s.x * (1.f / NC), mu1 = s.y * (1.f / NC);
        float v0 = q.x * (1.f / NC) - mu0 * mu0;
        float v1 = q.y * (1.f / NC) - mu1 * mu1;
        smu[tx] = make_float2(mu0, mu1);
        srs[tx] = make_float2(rsqrtf(v0 + 1e-5f), rsqrtf(v1 + 1e-5f));
    }
    __syncthreads();
    float2 mu = smu[tx], rs = srs[tx];
#pragma unroll
    for (int q = 0; q < 64; q++) {
        int c = ty + 4 * q;
        __half2 h = *(__half2*)&r[q];
        float2 f = __half22float2(h);
        float gg = g[c], bbv = bt[c];
        float o0 = (f.x - mu.x) * rs.x * gg + bbv;
        float o1 = (f.y - mu.y) * rs.y * gg + bbv;
        *(float2*)&out[(size_t)(b * NC + c) * 8192 + l0 + 2 * tx] = make_float2(o0, o1);
    }
}

// ---------------- launch (single stream) ----------------
static void* sym_addr(const void* sym) {
    void* p = nullptr;
    cudaGetSymbolAddress(&p, sym);
    return p;
}

extern "C" void kernel_launch(void* const* d_in, const int* in_sizes, int n_in,
                              void* d_out, int out_size) {
    const float* x     = (const float*)d_in[0];
    const float* ab_w1 = (const float*)d_in[1];
    const float* ab_b1 = (const float*)d_in[2];
    const float* ab_w2 = (const float*)d_in[3];
    const float* ab_b2 = (const float*)d_in[4];
    const float* db_w1 = (const float*)d_in[5];
    const float* db_b1 = (const float*)d_in[6];
    const float* db_w2 = (const float*)d_in[7];
    const float* db_b2 = (const float*)d_in[8];
    const float* ln_g  = (const float*)d_in[9];
    const float* ln_b  = (const float*)d_in[10];
    float* out = (float*)d_out;

    __half* D1 = (__half*)sym_addr(g_D1);
    __half* D2 = (__half*)sym_addr(g_D2);
    __half* D3 = (__half*)sym_addr(g_D3);
    __half* A3 = (__half*)sym_addr(g_A3);
    __half* S  = (__half*)sym_addr(g_S);
    __half* Wh = (__half*)sym_addr(g_Wh);

    cudaFuncSetAttribute(resblock_all, cudaFuncAttributeMaxDynamicSharedMemorySize, RS_SMEM);
    cudaFuncSetAttribute(fused_dwt,  cudaFuncAttributeMaxDynamicSharedMemorySize, DWT_SMEM_F * 4);
    cudaFuncSetAttribute(fused_idwt, cudaFuncAttributeMaxDynamicSharedMemorySize, IDWT_SMEM_B);

    const int ROWS = NB * NC;   // 4096

    convw_kernel<<<64, 256>>>(ab_w1, ab_w2, db_w1, db_w2, Wh);

    fused_dwt<<<ROWS, 512, DWT_SMEM_F * 4>>>(x, D1, D2, D3, A3);

    resblock_all<<<1024, 512, RS_SMEM>>>(D3, A3, D2, D1, Wh,
                                         ab_b1, ab_b2, db_b1, db_b2);

    fused_idwt<<<ROWS, 512, IDWT_SMEM_B>>>(A3, D3, D2, D1, x, S);

    ln_kernel<<<dim3(8192 / 128, NB), 256>>>(S, ln_g, ln_b, out);
}

// round 11
// speedup vs baseline: 1.0057x; 1.0057x over previous
#include <cuda_runtime.h>
#include <cuda_fp16.h>
#include <cstdint>
#include <math.h>

#define NB 16
#define NC 256

// ---------------- scratch (device globals: no allocs allowed) ----------------
__device__ __half g_D1[NB*NC*4096];
__device__ __half g_D2[NB*NC*2048];
__device__ __half g_D3[NB*NC*1024];
__device__ __half g_A3[NB*NC*1024];
__device__ __half g_S [NB*NC*8192];
__device__ __half g_Wh[4*NC*NC];    // fp16 weights: ab_w1, ab_w2, db_w1, db_w2

// ---------------- db4 filters ----------------
__constant__ float c_dec_lo[8] = {-0.010597401785069032f, 0.0328830116668852f, 0.030841381835560764f, -0.18703481171888114f, -0.027983769416859854f, 0.6308807679298589f, 0.7148465705529157f, 0.2303778133088965f};
__constant__ float c_dec_hi[8] = {-0.2303778133088965f, 0.7148465705529157f, -0.6308807679298589f, -0.027983769416859854f, 0.18703481171888114f, 0.030841381835560764f, -0.0328830116668852f, -0.010597401785069032f};
__constant__ float c_rec_lo[8] = {0.2303778133088965f, 0.7148465705529157f, 0.6308807679298589f, -0.027983769416859854f, -0.18703481171888114f, 0.030841381835560764f, 0.0328830116668852f, -0.010597401785069032f};
__constant__ float c_rec_hi[8] = {-0.010597401785069032f, -0.0328830116668852f, 0.030841381835560764f, 0.18703481171888114f, -0.027983769416859854f, -0.6308807679298589f, 0.7148465705529157f, -0.2303778133088965f};

// ================= helpers =================
__device__ __forceinline__ uint32_t smem_u32(const void* p) {
    uint32_t a;
    asm("{ .reg .u64 t; cvta.to.shared.u64 t, %1; cvt.u32.u64 %0, t; }" : "=r"(a) : "l"(p));
    return a;
}
__device__ __forceinline__ void cp16(uint32_t dst, const void* src) {
    asm volatile("cp.async.cg.shared.global [%0], [%1], 16;" :: "r"(dst), "l"(src));
}
__device__ __forceinline__ void cp_commit() { asm volatile("cp.async.commit_group;" ::: "memory"); }
__device__ __forceinline__ void cp_wait2()  { asm volatile("cp.async.wait_group 2;" ::: "memory"); }

__device__ __forceinline__ void mma_f16(float* c, const uint32_t* a, const uint32_t* b) {
    asm volatile("mma.sync.aligned.m16n8k16.row.col.f32.f16.f16.f32 "
                 "{%0,%1,%2,%3}, {%4,%5,%6,%7}, {%8,%9}, {%0,%1,%2,%3};"
                 : "+f"(c[0]), "+f"(c[1]), "+f"(c[2]), "+f"(c[3])
                 : "r"(a[0]), "r"(a[1]), "r"(a[2]), "r"(a[3]), "r"(b[0]), "r"(b[1]));
}
__device__ __forceinline__ void ldsm4(uint32_t* r, uint32_t addr) {
    asm volatile("ldmatrix.sync.aligned.m8n8.x4.shared.b16 {%0,%1,%2,%3}, [%4];"
                 : "=r"(r[0]), "=r"(r[1]), "=r"(r[2]), "=r"(r[3]) : "r"(addr));
}
__device__ __forceinline__ void ldsm4t(uint32_t* r, uint32_t addr) {
    asm volatile("ldmatrix.sync.aligned.m8n8.x4.trans.shared.b16 {%0,%1,%2,%3}, [%4];"
                 : "=r"(r[0]), "=r"(r[1]), "=r"(r[2]), "=r"(r[3]) : "r"(addr));
}
__device__ __forceinline__ float gelu_tanh(float x) {
    const float k0 = 0.7978845608028654f;
    const float k1 = 0.044715f;
    float x3 = x * x * x;
    float t = tanhf(k0 * (x + k1 * x3));
    return 0.5f * x * (1.f + t);
}

// ---------------- convert weights to fp16 ----------------
__global__ __launch_bounds__(256) void convw_kernel(const float* __restrict__ w0,
                                                    const float* __restrict__ w1,
                                                    const float* __restrict__ w2,
                                                    const float* __restrict__ w3,
                                                    __half* __restrict__ out) {
    int i = blockIdx.x * 256 + threadIdx.x;
    const float* src[4] = {w0, w1, w2, w3};
#pragma unroll
    for (int m = 0; m < 4; m++) {
        float4 v = *(const float4*)(src[m] + i * 4);
        __half2 h0 = __floats2half2_rn(v.x, v.y);
        __half2 h1 = __floats2half2_rn(v.z, v.w);
        uint2 pk = make_uint2(*(uint32_t*)&h0, *(uint32_t*)&h1);
        *(uint2*)(out + m * 65536 + i * 4) = pk;
    }
}

// ================= fused 3-level DWT (1 output/thread, stride-1 conflict-free) =================
#define DWT_SMEM_F (2*4104 + 2*2056 + 2*1032)

__device__ __forceinline__ void dwt_level_h(const float* __restrict__ E, const float* __restrict__ O,
                                            int Lh, __half* __restrict__ dOut,
                                            float* EO, float* OO, __half* aOut) {
    for (int j = threadIdx.x; j < Lh; j += 512) {
        const float* e = E + 4 + j;
        const float* o = O + 4 + j;
        float a, d;
        a = e[-1]*c_dec_lo[1]; a = fmaf(e[0], c_dec_lo[3], a); a = fmaf(e[1], c_dec_lo[5], a);
        a = fmaf(e[2], c_dec_lo[7], a); a = fmaf(o[-2], c_dec_lo[0], a); a = fmaf(o[-1], c_dec_lo[2], a);
        a = fmaf(o[0], c_dec_lo[4], a); a = fmaf(o[1], c_dec_lo[6], a);
        d = e[-1]*c_dec_hi[1]; d = fmaf(e[0], c_dec_hi[3], d); d = fmaf(e[1], c_dec_hi[5], d);
        d = fmaf(e[2], c_dec_hi[7], d); d = fmaf(o[-2], c_dec_hi[0], d); d = fmaf(o[-1], c_dec_hi[2], d);
        d = fmaf(o[0], c_dec_hi[4], d); d = fmaf(o[1], c_dec_hi[6], d);
        dOut[j] = __float2half(d);
        if (aOut) aOut[j] = __float2half(a);
        else { if (j & 1) OO[4 + (j >> 1)] = a; else EO[4 + (j >> 1)] = a; }
    }
}

__global__ __launch_bounds__(512) void fused_dwt(const float* __restrict__ x,
                                                 __half* __restrict__ D1,
                                                 __half* __restrict__ D2,
                                                 __half* __restrict__ D3,
                                                 __half* __restrict__ A3) {
    extern __shared__ float sm[];
    float* E1 = sm;            // 4104
    float* O1 = sm + 4104;
    float* E2 = sm + 8208;     // 2056
    float* O2 = sm + 10264;
    float* E3 = sm + 12320;    // 1032
    float* O3 = sm + 13352;
    int row = blockIdx.x, tid = threadIdx.x;

    if (tid < 48) {            // zero pads
        int a = tid >> 3, p = tid & 7;
        float* bases[6] = {E1, O1, E2, O2, E3, O3};
        int lens[6] = {4096, 4096, 2048, 2048, 1024, 1024};
        bases[a][p < 4 ? p : lens[a] + p] = 0.f;
    }
    const float4* x4 = (const float4*)(x + (size_t)row * 8192);
    for (int i = tid; i < 2048; i += 512) {
        float4 v = x4[i];
        *(float2*)&E1[4 + 2*i] = make_float2(v.x, v.z);
        *(float2*)&O1[4 + 2*i] = make_float2(v.y, v.w);
    }
    __syncthreads();
    dwt_level_h(E1, O1, 4096, D1 + (size_t)row * 4096, E2, O2, nullptr);
    __syncthreads();
    dwt_level_h(E2, O2, 2048, D2 + (size_t)row * 2048, E3, O3, nullptr);
    __syncthreads();
    dwt_level_h(E3, O3, 1024, D3 + (size_t)row * 1024, nullptr, nullptr, A3 + (size_t)row * 1024);
}

// ================= fused 3-level IDWT + skip, quad-processed, conflict-free =================
#define IDWT_A3H 0
#define IDWT_D3H 2080
#define IDWT_D2H 4160
#define IDWT_D1H 8288
#define IDWT_Y2  16512
#define IDWT_Y1  24736
#define IDWT_SMEM_B 41152

__global__ __launch_bounds__(512) void fused_idwt(const __half* __restrict__ A3v,
                                                  const __half* __restrict__ D3v,
                                                  const __half* __restrict__ D2v,
                                                  const __half* __restrict__ D1v,
                                                  const float* __restrict__ x,
                                                  __half* __restrict__ S) {
    extern __shared__ char smc[];
    __half* A3h = (__half*)(smc + IDWT_A3H);
    __half* D3h = (__half*)(smc + IDWT_D3H);
    __half* D2h = (__half*)(smc + IDWT_D2H);
    __half* D1h = (__half*)(smc + IDWT_D1H);
    float*  Y2  = (float*)(smc + IDWT_Y2);
    float*  Y1  = (float*)(smc + IDWT_Y1);
    int row = blockIdx.x, tid = threadIdx.x;

    if (tid < 8) {
        __half* hb[4] = {A3h, D3h, D2h, D1h};
        int hl[4] = {1024, 1024, 2048, 4096};
        int a = tid >> 1, e = tid & 1;
        uint4 z = make_uint4(0, 0, 0, 0);
        *(uint4*)&hb[a][e ? 8 + hl[a] : 0] = z;
    } else if (tid < 12) {
        float* fb[2] = {Y2, Y1};
        int fl[2] = {2048, 4096};
        int a = (tid - 8) >> 1, e = tid & 1;
        *(float4*)&fb[a][e ? 4 + fl[a] : 0] = make_float4(0.f, 0.f, 0.f, 0.f);
    }
    {
        const uint4* a3 = (const uint4*)(A3v + (size_t)row * 1024);
        const uint4* d3 = (const uint4*)(D3v + (size_t)row * 1024);
        const uint4* d2 = (const uint4*)(D2v + (size_t)row * 2048);
        const uint4* d1 = (const uint4*)(D1v + (size_t)row * 4096);
        if (tid < 128)       *(uint4*)&A3h[8 + 8 * tid] = a3[tid];
        else if (tid < 256)  *(uint4*)&D3h[8 + 8 * (tid - 128)] = d3[tid - 128];
        else                 *(uint4*)&D2h[8 + 8 * (tid - 256)] = d2[tid - 256];
        *(uint4*)&D1h[8 + 8 * tid] = d1[tid];
    }
    __syncthreads();

    {
        int i = tid;
        float2 am = __half22float2(*(const __half2*)&A3h[6 + 2*i]);
        float2 ac = __half22float2(*(const __half2*)&A3h[8 + 2*i]);
        float2 ap = __half22float2(*(const __half2*)&A3h[10 + 2*i]);
        float2 dm = __half22float2(*(const __half2*)&D3h[6 + 2*i]);
        float2 dc = __half22float2(*(const __half2*)&D3h[8 + 2*i]);
        float2 dp = __half22float2(*(const __half2*)&D3h[10 + 2*i]);
        float y0 = am.x*c_rec_lo[7] + am.y*c_rec_lo[5] + ac.x*c_rec_lo[3] + ac.y*c_rec_lo[1]
                 + dm.x*c_rec_hi[7] + dm.y*c_rec_hi[5] + dc.x*c_rec_hi[3] + dc.y*c_rec_hi[1];
        float y1 = am.y*c_rec_lo[6] + ac.x*c_rec_lo[4] + ac.y*c_rec_lo[2] + ap.x*c_rec_lo[0]
                 + dm.y*c_rec_hi[6] + dc.x*c_rec_hi[4] + dc.y*c_rec_hi[2] + dp.x*c_rec_hi[0];
        float y2 = am.y*c_rec_lo[7] + ac.x*c_rec_lo[5] + ac.y*c_rec_lo[3] + ap.x*c_rec_lo[1]
                 + dm.y*c_rec_hi[7] + dc.x*c_rec_hi[5] + dc.y*c_rec_hi[3] + dp.x*c_rec_hi[1];
        float y3 = ac.x*c_rec_lo[6] + ac.y*c_rec_lo[4] + ap.x*c_rec_lo[2] + ap.y*c_rec_lo[0]
                 + dc.x*c_rec_hi[6] + dc.y*c_rec_hi[4] + dp.x*c_rec_hi[2] + dp.y*c_rec_hi[0];
        *(float4*)&Y2[4 + 4*i] = make_float4(y0, y1, y2, y3);
    }
    __syncthreads();

#pragma unroll
    for (int q = 0; q < 2; q++) {
        int i = tid + q * 512;
        float2 am = *(const float2*)&Y2[2 + 2*i];
        float2 ac = *(const float2*)&Y2[4 + 2*i];
        float2 ap = *(const float2*)&Y2[6 + 2*i];
        float2 dm = __half22float2(*(const __half2*)&D2h[6 + 2*i]);
        float2 dc = __half22float2(*(const __half2*)&D2h[8 + 2*i]);
        float2 dp = __half22float2(*(const __half2*)&D2h[10 + 2*i]);
        float y0 = am.x*c_rec_lo[7] + am.y*c_rec_lo[5] + ac.x*c_rec_lo[3] + ac.y*c_rec_lo[1]
                 + dm.x*c_rec_hi[7] + dm.y*c_rec_hi[5] + dc.x*c_rec_hi[3] + dc.y*c_rec_hi[1];
        float y1 = am.y*c_rec_lo[6] + ac.x*c_rec_lo[4] + ac.y*c_rec_lo[2] + ap.x*c_rec_lo[0]
                 + dm.y*c_rec_hi[6] + dc.x*c_rec_hi[4] + dc.y*c_rec_hi[2] + dp.x*c_rec_hi[0];
        float y2 = am.y*c_rec_lo[7] + ac.x*c_rec_lo[5] + ac.y*c_rec_lo[3] + ap.x*c_rec_lo[1]
                 + dm.y*c_rec_hi[7] + dc.x*c_rec_hi[5] + dc.y*c_rec_hi[3] + dp.x*c_rec_hi[1];
        float y3 = ac.x*c_rec_lo[6] + ac.y*c_rec_lo[4] + ap.x*c_rec_lo[2] + ap.y*c_rec_lo[0]
                 + dc.x*c_rec_hi[6] + dc.y*c_rec_hi[4] + dp.x*c_rec_hi[2] + dp.y*c_rec_hi[0];
        *(float4*)&Y1[4 + 4*i] = make_float4(y0, y1, y2, y3);
    }
    __syncthreads();

    const float* xr = x + (size_t)row * 8192;
    __half* Sr = S + (size_t)row * 8192;
#pragma unroll
    for (int q = 0; q < 4; q++) {
        int i = tid + q * 512;
        float2 am = *(const float2*)&Y1[2 + 2*i];
        float2 ac = *(const float2*)&Y1[4 + 2*i];
        float2 ap = *(const float2*)&Y1[6 + 2*i];
        float2 dm = __half22float2(*(const __half2*)&D1h[6 + 2*i]);
        float2 dc = __half22float2(*(const __half2*)&D1h[8 + 2*i]);
        float2 dp = __half22float2(*(const __half2*)&D1h[10 + 2*i]);
        float y0 = am.x*c_rec_lo[7] + am.y*c_rec_lo[5] + ac.x*c_rec_lo[3] + ac.y*c_rec_lo[1]
                 + dm.x*c_rec_hi[7] + dm.y*c_rec_hi[5] + dc.x*c_rec_hi[3] + dc.y*c_rec_hi[1];
        float y1 = am.y*c_rec_lo[6] + ac.x*c_rec_lo[4] + ac.y*c_rec_lo[2] + ap.x*c_rec_lo[0]
                 + dm.y*c_rec_hi[6] + dc.x*c_rec_hi[4] + dc.y*c_rec_hi[2] + dp.x*c_rec_hi[0];
        float y2 = am.y*c_rec_lo[7] + ac.x*c_rec_lo[5] + ac.y*c_rec_lo[3] + ap.x*c_rec_lo[1]
                 + dm.y*c_rec_hi[7] + dc.x*c_rec_hi[5] + dc.y*c_rec_hi[3] + dp.x*c_rec_hi[1];
        float y3 = ac.x*c_rec_lo[6] + ac.y*c_rec_lo[4] + ap.x*c_rec_lo[2] + ap.y*c_rec_lo[0]
                 + dc.x*c_rec_hi[6] + dc.y*c_rec_hi[4] + dp.x*c_rec_hi[2] + dp.y*c_rec_hi[0];
        float4 xv = *(const float4*)&xr[4*i];
        __half2 h0 = __floats2half2_rn(y0 + xv.x, y1 + xv.y);
        __half2 h1 = __floats2half2_rn(y2 + xv.z, y3 + xv.w);
        uint2 pk = make_uint2(*(uint32_t*)&h0, *(uint32_t*)&h1);
        *(uint2*)&Sr[4*i] = pk;
    }
}

// ================= combined fused res blocks (round-8 structure) =================
#define A_STAGE_B (256*80)      // 20480
#define B_STAGE_B (32*272)      // 8704
#define H_BYTES   (256*272)     // 69632
#define RS_SMEM   (4*A_STAGE_B + 8*B_STAGE_B + H_BYTES)   // 221184

__global__ __launch_bounds__(512, 1) void resblock_all(
        __half* __restrict__ D3, __half* __restrict__ A3,
        __half* __restrict__ D2, __half* __restrict__ D1,
        const __half* __restrict__ Wh,
        const float* __restrict__ ab_b1, const float* __restrict__ ab_b2,
        const float* __restrict__ db_b1, const float* __restrict__ db_b2) {
    extern __shared__ char smem[];
    uint32_t sA = smem_u32(smem);
    uint32_t sB = sA + 4 * A_STAGE_B;
    uint32_t sH = sB + 8 * B_STAGE_B;

    int tid = threadIdx.x;
    int wid = tid >> 5, lane = tid & 31;
    int wm = wid >> 2, wn = wid & 3;
    int g = lane >> 2, tt = lane & 3;
    int l15 = lane & 15, lhi = (lane >> 4) << 4;

    int id = blockIdx.x;
    int b = id >> 6, slot = id & 63;
    __half* X; int L, ln;
    const __half *W1, *W2; const float *b1, *b2;
    if (slot < 8)       { X = D3; L = 1024; ln = slot * 128;        W1 = Wh + 2*65536; W2 = Wh + 3*65536; b1 = db_b1; b2 = db_b2; }
    else if (slot < 16) { X = A3; L = 1024; ln = (slot - 8) * 128;  W1 = Wh + 0*65536; W2 = Wh + 1*65536; b1 = ab_b1; b2 = ab_b2; }
    else if (slot < 32) { X = D2; L = 2048; ln = (slot - 16) * 128; W1 = Wh + 2*65536; W2 = Wh + 3*65536; b1 = db_b1; b2 = db_b2; }
    else                { X = D1; L = 4096; ln = (slot - 32) * 128; W1 = Wh + 2*65536; W2 = Wh + 3*65536; b1 = db_b1; b2 = db_b2; }
    __half* Xb = X + (size_t)b * NC * L + ln;

    float acc[4][4][4];
#pragma unroll
    for (int mt = 0; mt < 4; mt++)
#pragma unroll
        for (int nt = 0; nt < 4; nt++)
#pragma unroll
            for (int r = 0; r < 4; r++) acc[mt][nt][r] = 0.f;

    auto loadAB = [&](int c, int s) {
        const __half* wsrc = (c < 8 ? W1 : W2) + (c & 7) * 32;
#pragma unroll
        for (int q = 0; q < 2; q++) {
            int idx = tid + q * 512;
            int r = idx >> 2, u = idx & 3;
            cp16(sA + s * A_STAGE_B + r * 80 + u * 16, wsrc + r * 256 + u * 8);
        }
        if (c < 8) {
            int k = tid >> 4, u = tid & 15;
            cp16(sB + c * B_STAGE_B + k * 272 + u * 16,
                 Xb + (size_t)(c * 32 + k) * L + u * 8);
        }
    };
    auto compute = [&](int c, int s) {
        uint32_t Abase = sA + s * A_STAGE_B + (wm * 64) * 80;
        uint32_t Bbase = (c < 8) ? (sB + (uint32_t)c * B_STAGE_B)
                                 : (sH + (uint32_t)(c - 8) * 32 * 272);
#pragma unroll
        for (int kk = 0; kk < 2; kk++) {
            uint32_t a[4][4];
#pragma unroll
            for (int mt = 0; mt < 4; mt++)
                ldsm4(a[mt], Abase + (mt * 16 + l15) * 80 + kk * 32 + lhi);
            uint32_t bf[2][4];
#pragma unroll
            for (int p = 0; p < 2; p++)
                ldsm4t(bf[p], Bbase + (kk * 16 + l15) * 272 + (wn * 32 + p * 16) * 2 + lhi);
#pragma unroll
            for (int mt = 0; mt < 4; mt++)
#pragma unroll
                for (int nt = 0; nt < 4; nt++)
                    mma_f16(acc[mt][nt], a[mt], &bf[nt >> 1][(nt & 1) * 2]);
        }
    };

    loadAB(0, 0); cp_commit();
    loadAB(1, 1); cp_commit();
    loadAB(2, 2); cp_commit();

#pragma unroll 1
    for (int c = 0; c < 16; c++) {
        int s = c & 3;
        cp_wait2();
        __syncthreads();
        if (c + 3 < 16) loadAB(c + 3, (c + 3) & 3);
        cp_commit();
        compute(c, s);
        if (c == 7) {
#pragma unroll
            for (int mt = 0; mt < 4; mt++)
#pragma unroll
                for (int hh = 0; hh < 2; hh++) {
                    int m = wm * 64 + mt * 16 + g + hh * 8;
                    float bb = b1[m];
#pragma unroll
                    for (int nt = 0; nt < 4; nt++) {
                        float v0 = gelu_tanh(acc[mt][nt][hh * 2 + 0] + bb);
                        float v1 = gelu_tanh(acc[mt][nt][hh * 2 + 1] + bb);
                        __half2 h = __floats2half2_rn(v0, v1);
                        asm volatile("st.shared.b32 [%0], %1;"
                                     :: "r"(sH + m * 272 + (wn * 32 + nt * 8 + tt * 2) * 2),
                                        "r"(*(uint32_t*)&h));
                        acc[mt][nt][hh * 2 + 0] = 0.f;
                        acc[mt][nt][hh * 2 + 1] = 0.f;
                    }
                }
        }
    }

    // ---- epilogue: X(gmem) = X(smem-resident) + acc + b2 ----
#pragma unroll
    for (int mt = 0; mt < 4; mt++)
#pragma unroll
        for (int hh = 0; hh < 2; hh++) {
            int m = wm * 64 + mt * 16 + g + hh * 8;
            float bb = b2[m];
            size_t orow = (size_t)m * L;
            uint32_t xrow = sB + (uint32_t)(m >> 5) * B_STAGE_B + (uint32_t)(m & 31) * 272;
#pragma unroll
            for (int nt = 0; nt < 4; nt++) {
                int col = wn * 32 + nt * 8 + tt * 2;
                uint32_t xv;
                asm volatile("ld.shared.b32 %0, [%1];" : "=r"(xv) : "r"(xrow + col * 2));
                float2 rr = __half22float2(*(__half2*)&xv);
                float v0 = acc[mt][nt][hh * 2 + 0] + bb + rr.x;
                float v1 = acc[mt][nt][hh * 2 + 1] + bb + rr.y;
                *(__half2*)&Xb[orow + col] = __floats2half2_rn(v0, v1);
            }
        }
}

// ---------------- LayerNorm over channels: fp16 in, fp32 out ----------------
__global__ __launch_bounds__(256) void ln_kernel(const __half* __restrict__ S,
                                                 const float* __restrict__ g,
                                                 const float* __restrict__ bt,
                                                 float* __restrict__ out) {
    int b = blockIdx.y;
    int l0 = blockIdx.x * 128;
    int tx = threadIdx.x & 63;
    int ty = threadIdx.x >> 6;
    const __half2* Sb = (const __half2*)S;
    uint32_t r[64];
    float s0 = 0.f, s1 = 0.f, q0 = 0.f, q1 = 0.f;
#pragma unroll
    for (int q = 0; q < 64; q++) {
        int c = ty + 4 * q;
        __half2 h = Sb[(size_t)(b * NC + c) * 4096 + (l0 >> 1) + tx];
        r[q] = *(uint32_t*)&h;
        float2 f = __half22float2(h);
        s0 += f.x; s1 += f.y;
        q0 = fmaf(f.x, f.x, q0);
        q1 = fmaf(f.y, f.y, q1);
    }
    __shared__ float2 ssum[4][64], ssq[4][64];
    __shared__ float2 smu[64], srs[64];
    ssum[ty][tx] = make_float2(s0, s1);
    ssq[ty][tx] = make_float2(q0, q1);
    __syncthreads();
    if (ty == 0) {
        float2 s = ssum[0][tx], q = ssq[0][tx];
#pragma unroll
        for (int t = 1; t < 4; t++) {
            s.x += ssum[t][tx].x; s.y += ssum[t][tx].y;
            q.x += ssq[t][tx].x;  q.y += ssq[t][tx].y;
        }
        float mu0 = s.x * (1.f / NC), mu1 = s.y * (1.f / NC);
        float v0 = q.x * (1.f / NC) - mu0 * mu0;
        float v1 = q.y * (1.f / NC) - mu1 * mu1;
        smu[tx] = make_float2(mu0, mu1);
        srs[tx] = make_float2(rsqrtf(v0 + 1e-5f), rsqrtf(v1 + 1e-5f));
    }
    __syncthreads();
    float2 mu = smu[tx], rs = srs[tx];
#pragma unroll
    for (int q = 0; q < 64; q++) {
        int c = ty + 4 * q;
        __half2 h = *(__half2*)&r[q];
        float2 f = __half22float2(h);
        float gg = g[c], bbv = bt[c];
        float o0 = (f.x - mu.x) * rs.x * gg + bbv;
        float o1 = (f.y - mu.y) * rs.y * gg + bbv;
        *(float2*)&out[(size_t)(b * NC + c) * 8192 + l0 + 2 * tx] = make_float2(o0, o1);
    }
}

// ---------------- launch (single stream) ----------------
static void* sym_addr(const void* sym) {
    void* p = nullptr;
    cudaGetSymbolAddress(&p, sym);
    return p;
}

extern "C" void kernel_launch(void* const* d_in, const int* in_sizes, int n_in,
                              void* d_out, int out_size) {
    const float* x     = (const float*)d_in[0];
    const float* ab_w1 = (const float*)d_in[1];
    const float* ab_b1 = (const float*)d_in[2];
    const float* ab_w2 = (const float*)d_in[3];
    const float* ab_b2 = (const float*)d_in[4];
    const float* db_w1 = (const float*)d_in[5];
    const float* db_b1 = (const float*)d_in[6];
    const float* db_w2 = (const float*)d_in[7];
    const float* db_b2 = (const float*)d_in[8];
    const float* ln_g  = (const float*)d_in[9];
    const float* ln_b  = (const float*)d_in[10];
    float* out = (float*)d_out;

    __half* D1 = (__half*)sym_addr(g_D1);
    __half* D2 = (__half*)sym_addr(g_D2);
    __half* D3 = (__half*)sym_addr(g_D3);
    __half* A3 = (__half*)sym_addr(g_A3);
    __half* S  = (__half*)sym_addr(g_S);
    __half* Wh = (__half*)sym_addr(g_Wh);

    cudaFuncSetAttribute(resblock_all, cudaFuncAttributeMaxDynamicSharedMemorySize, RS_SMEM);
    cudaFuncSetAttribute(fused_dwt,  cudaFuncAttributeMaxDynamicSharedMemorySize, DWT_SMEM_F * 4);
    cudaFuncSetAttribute(fused_idwt, cudaFuncAttributeMaxDynamicSharedMemorySize, IDWT_SMEM_B);

    const int ROWS = NB * NC;   // 4096

    convw_kernel<<<64, 256>>>(ab_w1, ab_w2, db_w1, db_w2, Wh);

    fused_dwt<<<ROWS, 512, DWT_SMEM_F * 4>>>(x, D1, D2, D3, A3);

    resblock_all<<<1024, 512, RS_SMEM>>>(D3, A3, D2, D1, Wh,
                                         ab_b1, ab_b2, db_b1, db_b2);

    fused_idwt<<<ROWS, 512, IDWT_SMEM_B>>>(A3, D3, D2, D1, x, S);

    ln_kernel<<<dim3(8192 / 128, NB), 256>>>(S, ln_g, ln_b, out);
}

// round 12
// speedup vs baseline: 1.0147x; 1.0090x over previous
#include <cuda_runtime.h>
#include <cuda_fp16.h>
#include <cstdint>
#include <math.h>

#define NB 16
#define NC 256

// ---------------- scratch (device globals: no allocs allowed) ----------------
__device__ __half g_D1[NB*NC*4096];
__device__ __half g_D2[NB*NC*2048];
__device__ __half g_D3[NB*NC*1024];
__device__ __half g_A3[NB*NC*1024];
__device__ __half g_S [NB*NC*8192];
__device__ __half g_Wh[4*NC*NC];    // fp16 weights: ab_w1, ab_w2, db_w1, db_w2

// ---------------- db4 filters ----------------
__constant__ float c_dec_lo[8] = {-0.010597401785069032f, 0.0328830116668852f, 0.030841381835560764f, -0.18703481171888114f, -0.027983769416859854f, 0.6308807679298589f, 0.7148465705529157f, 0.2303778133088965f};
__constant__ float c_dec_hi[8] = {-0.2303778133088965f, 0.7148465705529157f, -0.6308807679298589f, -0.027983769416859854f, 0.18703481171888114f, 0.030841381835560764f, -0.0328830116668852f, -0.010597401785069032f};
__constant__ float c_rec_lo[8] = {0.2303778133088965f, 0.7148465705529157f, 0.6308807679298589f, -0.027983769416859854f, -0.18703481171888114f, 0.030841381835560764f, 0.0328830116668852f, -0.010597401785069032f};
__constant__ float c_rec_hi[8] = {-0.010597401785069032f, -0.0328830116668852f, 0.030841381835560764f, 0.18703481171888114f, -0.027983769416859854f, -0.6308807679298589f, 0.7148465705529157f, -0.2303778133088965f};

// ================= helpers =================
__device__ __forceinline__ uint32_t smem_u32(const void* p) {
    uint32_t a;
    asm("{ .reg .u64 t; cvta.to.shared.u64 t, %1; cvt.u32.u64 %0, t; }" : "=r"(a) : "l"(p));
    return a;
}
__device__ __forceinline__ void cp16(uint32_t dst, const void* src) {
    asm volatile("cp.async.cg.shared.global [%0], [%1], 16;" :: "r"(dst), "l"(src));
}
__device__ __forceinline__ void cp_commit() { asm volatile("cp.async.commit_group;" ::: "memory"); }
__device__ __forceinline__ void cp_wait0()  { asm volatile("cp.async.wait_group 0;" ::: "memory"); }

__device__ __forceinline__ void mma_f16(float* c, const uint32_t* a, const uint32_t* b) {
    asm volatile("mma.sync.aligned.m16n8k16.row.col.f32.f16.f16.f32 "
                 "{%0,%1,%2,%3}, {%4,%5,%6,%7}, {%8,%9}, {%0,%1,%2,%3};"
                 : "+f"(c[0]), "+f"(c[1]), "+f"(c[2]), "+f"(c[3])
                 : "r"(a[0]), "r"(a[1]), "r"(a[2]), "r"(a[3]), "r"(b[0]), "r"(b[1]));
}
__device__ __forceinline__ void ldsm4(uint32_t* r, uint32_t addr) {
    asm volatile("ldmatrix.sync.aligned.m8n8.x4.shared.b16 {%0,%1,%2,%3}, [%4];"
                 : "=r"(r[0]), "=r"(r[1]), "=r"(r[2]), "=r"(r[3]) : "r"(addr));
}
__device__ __forceinline__ void ldsm4t(uint32_t* r, uint32_t addr) {
    asm volatile("ldmatrix.sync.aligned.m8n8.x4.trans.shared.b16 {%0,%1,%2,%3}, [%4];"
                 : "=r"(r[0]), "=r"(r[1]), "=r"(r[2]), "=r"(r[3]) : "r"(addr));
}
__device__ __forceinline__ float gelu_tanh(float x) {
    const float k0 = 0.7978845608028654f;
    const float k1 = 0.044715f;
    float x3 = x * x * x;
    float t = tanhf(k0 * (x + k1 * x3));
    return 0.5f * x * (1.f + t);
}

// ---------------- convert weights to fp16 ----------------
__global__ __launch_bounds__(256) void convw_kernel(const float* __restrict__ w0,
                                                    const float* __restrict__ w1,
                                                    const float* __restrict__ w2,
                                                    const float* __restrict__ w3,
                                                    __half* __restrict__ out) {
    int i = blockIdx.x * 256 + threadIdx.x;
    const float* src[4] = {w0, w1, w2, w3};
#pragma unroll
    for (int m = 0; m < 4; m++) {
        float4 v = *(const float4*)(src[m] + i * 4);
        __half2 h0 = __floats2half2_rn(v.x, v.y);
        __half2 h1 = __floats2half2_rn(v.z, v.w);
        uint2 pk = make_uint2(*(uint32_t*)&h0, *(uint32_t*)&h1);
        *(uint2*)(out + m * 65536 + i * 4) = pk;
    }
}

// ================= fused 3-level DWT (round-8 pair-processed form) =================
#define DWT_SMEM_F (2*4104 + 2*2056 + 2*1032)

__device__ __forceinline__ void dwt_level_h(const float* __restrict__ E, const float* __restrict__ O,
                                            int Lh, __half* __restrict__ dOut,
                                            float* EO, float* OO, __half* aOut) {
    for (int i = threadIdx.x; i < (Lh >> 1); i += 512) {
        int j = 2 * i;
        const float* e = E + 4 + j;
        const float* o = O + 4 + j;
        float em1 = e[-1], e0 = e[0], e1 = e[1], e2 = e[2], e3 = e[3];
        float om2 = o[-2], om1 = o[-1], o0 = o[0], o1 = o[1], o2 = o[2];
        float a0 = em1*c_dec_lo[1] + e0*c_dec_lo[3] + e1*c_dec_lo[5] + e2*c_dec_lo[7]
                 + om2*c_dec_lo[0] + om1*c_dec_lo[2] + o0*c_dec_lo[4] + o1*c_dec_lo[6];
        float a1 = e0*c_dec_lo[1] + e1*c_dec_lo[3] + e2*c_dec_lo[5] + e3*c_dec_lo[7]
                 + om1*c_dec_lo[0] + o0*c_dec_lo[2] + o1*c_dec_lo[4] + o2*c_dec_lo[6];
        float d0 = em1*c_dec_hi[1] + e0*c_dec_hi[3] + e1*c_dec_hi[5] + e2*c_dec_hi[7]
                 + om2*c_dec_hi[0] + om1*c_dec_hi[2] + o0*c_dec_hi[4] + o1*c_dec_hi[6];
        float d1 = e0*c_dec_hi[1] + e1*c_dec_hi[3] + e2*c_dec_hi[5] + e3*c_dec_hi[7]
                 + om1*c_dec_hi[0] + o0*c_dec_hi[2] + o1*c_dec_hi[4] + o2*c_dec_hi[6];
        *(__half2*)&dOut[j] = __floats2half2_rn(d0, d1);
        if (aOut) *(__half2*)&aOut[j] = __floats2half2_rn(a0, a1);
        else { EO[4 + i] = a0; OO[4 + i] = a1; }
    }
}

__global__ __launch_bounds__(512) void fused_dwt(const float* __restrict__ x,
                                                 __half* __restrict__ D1,
                                                 __half* __restrict__ D2,
                                                 __half* __restrict__ D3,
                                                 __half* __restrict__ A3) {
    extern __shared__ float sm[];
    float* E1 = sm;            // 4104
    float* O1 = sm + 4104;
    float* E2 = sm + 8208;     // 2056
    float* O2 = sm + 10264;
    float* E3 = sm + 12320;    // 1032
    float* O3 = sm + 13352;
    int row = blockIdx.x, tid = threadIdx.x;

    if (tid < 48) {            // zero pads
        int a = tid >> 3, p = tid & 7;
        float* bases[6] = {E1, O1, E2, O2, E3, O3};
        int lens[6] = {4096, 4096, 2048, 2048, 1024, 1024};
        bases[a][p < 4 ? p : lens[a] + p] = 0.f;
    }
    const float4* x4 = (const float4*)(x + (size_t)row * 8192);
    for (int i = tid; i < 2048; i += 512) {
        float4 v = x4[i];
        *(float2*)&E1[4 + 2*i] = make_float2(v.x, v.z);
        *(float2*)&O1[4 + 2*i] = make_float2(v.y, v.w);
    }
    __syncthreads();
    dwt_level_h(E1, O1, 4096, D1 + (size_t)row * 4096, E2, O2, nullptr);
    __syncthreads();
    dwt_level_h(E2, O2, 2048, D2 + (size_t)row * 2048, E3, O3, nullptr);
    __syncthreads();
    dwt_level_h(E3, O3, 1024, D3 + (size_t)row * 1024, nullptr, nullptr, A3 + (size_t)row * 1024);
}

// ================= fused 3-level IDWT + skip, quad-processed, conflict-free =================
#define IDWT_A3H 0
#define IDWT_D3H 2080
#define IDWT_D2H 4160
#define IDWT_D1H 8288
#define IDWT_Y2  16512
#define IDWT_Y1  24736
#define IDWT_SMEM_B 41152

__global__ __launch_bounds__(512) void fused_idwt(const __half* __restrict__ A3v,
                                                  const __half* __restrict__ D3v,
                                                  const __half* __restrict__ D2v,
                                                  const __half* __restrict__ D1v,
                                                  const float* __restrict__ x,
                                                  __half* __restrict__ S) {
    extern __shared__ char smc[];
    __half* A3h = (__half*)(smc + IDWT_A3H);
    __half* D3h = (__half*)(smc + IDWT_D3H);
    __half* D2h = (__half*)(smc + IDWT_D2H);
    __half* D1h = (__half*)(smc + IDWT_D1H);
    float*  Y2  = (float*)(smc + IDWT_Y2);
    float*  Y1  = (float*)(smc + IDWT_Y1);
    int row = blockIdx.x, tid = threadIdx.x;

    if (tid < 8) {
        __half* hb[4] = {A3h, D3h, D2h, D1h};
        int hl[4] = {1024, 1024, 2048, 4096};
        int a = tid >> 1, e = tid & 1;
        uint4 z = make_uint4(0, 0, 0, 0);
        *(uint4*)&hb[a][e ? 8 + hl[a] : 0] = z;
    } else if (tid < 12) {
        float* fb[2] = {Y2, Y1};
        int fl[2] = {2048, 4096};
        int a = (tid - 8) >> 1, e = tid & 1;
        *(float4*)&fb[a][e ? 4 + fl[a] : 0] = make_float4(0.f, 0.f, 0.f, 0.f);
    }
    {
        const uint4* a3 = (const uint4*)(A3v + (size_t)row * 1024);
        const uint4* d3 = (const uint4*)(D3v + (size_t)row * 1024);
        const uint4* d2 = (const uint4*)(D2v + (size_t)row * 2048);
        const uint4* d1 = (const uint4*)(D1v + (size_t)row * 4096);
        if (tid < 128)       *(uint4*)&A3h[8 + 8 * tid] = a3[tid];
        else if (tid < 256)  *(uint4*)&D3h[8 + 8 * (tid - 128)] = d3[tid - 128];
        else                 *(uint4*)&D2h[8 + 8 * (tid - 256)] = d2[tid - 256];
        *(uint4*)&D1h[8 + 8 * tid] = d1[tid];
    }
    __syncthreads();

    {
        int i = tid;
        float2 am = __half22float2(*(const __half2*)&A3h[6 + 2*i]);
        float2 ac = __half22float2(*(const __half2*)&A3h[8 + 2*i]);
        float2 ap = __half22float2(*(const __half2*)&A3h[10 + 2*i]);
        float2 dm = __half22float2(*(const __half2*)&D3h[6 + 2*i]);
        float2 dc = __half22float2(*(const __half2*)&D3h[8 + 2*i]);
        float2 dp = __half22float2(*(const __half2*)&D3h[10 + 2*i]);
        float y0 = am.x*c_rec_lo[7] + am.y*c_rec_lo[5] + ac.x*c_rec_lo[3] + ac.y*c_rec_lo[1]
                 + dm.x*c_rec_hi[7] + dm.y*c_rec_hi[5] + dc.x*c_rec_hi[3] + dc.y*c_rec_hi[1];
        float y1 = am.y*c_rec_lo[6] + ac.x*c_rec_lo[4] + ac.y*c_rec_lo[2] + ap.x*c_rec_lo[0]
                 + dm.y*c_rec_hi[6] + dc.x*c_rec_hi[4] + dc.y*c_rec_hi[2] + dp.x*c_rec_hi[0];
        float y2 = am.y*c_rec_lo[7] + ac.x*c_rec_lo[5] + ac.y*c_rec_lo[3] + ap.x*c_rec_lo[1]
                 + dm.y*c_rec_hi[7] + dc.x*c_rec_hi[5] + dc.y*c_rec_hi[3] + dp.x*c_rec_hi[1];
        float y3 = ac.x*c_rec_lo[6] + ac.y*c_rec_lo[4] + ap.x*c_rec_lo[2] + ap.y*c_rec_lo[0]
                 + dc.x*c_rec_hi[6] + dc.y*c_rec_hi[4] + dp.x*c_rec_hi[2] + dp.y*c_rec_hi[0];
        *(float4*)&Y2[4 + 4*i] = make_float4(y0, y1, y2, y3);
    }
    __syncthreads();

#pragma unroll
    for (int q = 0; q < 2; q++) {
        int i = tid + q * 512;
        float2 am = *(const float2*)&Y2[2 + 2*i];
        float2 ac = *(const float2*)&Y2[4 + 2*i];
        float2 ap = *(const float2*)&Y2[6 + 2*i];
        float2 dm = __half22float2(*(const __half2*)&D2h[6 + 2*i]);
        float2 dc = __half22float2(*(const __half2*)&D2h[8 + 2*i]);
        float2 dp = __half22float2(*(const __half2*)&D2h[10 + 2*i]);
        float y0 = am.x*c_rec_lo[7] + am.y*c_rec_lo[5] + ac.x*c_rec_lo[3] + ac.y*c_rec_lo[1]
                 + dm.x*c_rec_hi[7] + dm.y*c_rec_hi[5] + dc.x*c_rec_hi[3] + dc.y*c_rec_hi[1];
        float y1 = am.y*c_rec_lo[6] + ac.x*c_rec_lo[4] + ac.y*c_rec_lo[2] + ap.x*c_rec_lo[0]
                 + dm.y*c_rec_hi[6] + dc.x*c_rec_hi[4] + dc.y*c_rec_hi[2] + dp.x*c_rec_hi[0];
        float y2 = am.y*c_rec_lo[7] + ac.x*c_rec_lo[5] + ac.y*c_rec_lo[3] + ap.x*c_rec_lo[1]
                 + dm.y*c_rec_hi[7] + dc.x*c_rec_hi[5] + dc.y*c_rec_hi[3] + dp.x*c_rec_hi[1];
        float y3 = ac.x*c_rec_lo[6] + ac.y*c_rec_lo[4] + ap.x*c_rec_lo[2] + ap.y*c_rec_lo[0]
                 + dc.x*c_rec_hi[6] + dc.y*c_rec_hi[4] + dp.x*c_rec_hi[2] + dp.y*c_rec_hi[0];
        *(float4*)&Y1[4 + 4*i] = make_float4(y0, y1, y2, y3);
    }
    __syncthreads();

    const float* xr = x + (size_t)row * 8192;
    __half* Sr = S + (size_t)row * 8192;
#pragma unroll
    for (int q = 0; q < 4; q++) {
        int i = tid + q * 512;
        float2 am = *(const float2*)&Y1[2 + 2*i];
        float2 ac = *(const float2*)&Y1[4 + 2*i];
        float2 ap = *(const float2*)&Y1[6 + 2*i];
        float2 dm = __half22float2(*(const __half2*)&D1h[6 + 2*i]);
        float2 dc = __half22float2(*(const __half2*)&D1h[8 + 2*i]);
        float2 dp = __half22float2(*(const __half2*)&D1h[10 + 2*i]);
        float y0 = am.x*c_rec_lo[7] + am.y*c_rec_lo[5] + ac.x*c_rec_lo[3] + ac.y*c_rec_lo[1]
                 + dm.x*c_rec_hi[7] + dm.y*c_rec_hi[5] + dc.x*c_rec_hi[3] + dc.y*c_rec_hi[1];
        float y1 = am.y*c_rec_lo[6] + ac.x*c_rec_lo[4] + ac.y*c_rec_lo[2] + ap.x*c_rec_lo[0]
                 + dm.y*c_rec_hi[6] + dc.x*c_rec_hi[4] + dc.y*c_rec_hi[2] + dp.x*c_rec_hi[0];
        float y2 = am.y*c_rec_lo[7] + ac.x*c_rec_lo[5] + ac.y*c_rec_lo[3] + ap.x*c_rec_lo[1]
                 + dm.y*c_rec_hi[7] + dc.x*c_rec_hi[5] + dc.y*c_rec_hi[3] + dp.x*c_rec_hi[1];
        float y3 = ac.x*c_rec_lo[6] + ac.y*c_rec_lo[4] + ap.x*c_rec_lo[2] + ap.y*c_rec_lo[0]
                 + dc.x*c_rec_hi[6] + dc.y*c_rec_hi[4] + dp.x*c_rec_hi[2] + dp.y*c_rec_hi[0];
        float4 xv = *(const float4*)&xr[4*i];
        __half2 h0 = __floats2half2_rn(y0 + xv.x, y1 + xv.y);
        __half2 h1 = __floats2half2_rn(y2 + xv.z, y3 + xv.w);
        uint2 pk = make_uint2(*(uint32_t*)&h0, *(uint32_t*)&h1);
        *(uint2*)&Sr[4*i] = pk;
    }
}

// ================= combined fused res blocks, batch-2 mainloop (8 barriers) =================
#define A_STAGE_B (256*80)      // 20480
#define B_STAGE_B (32*272)      // 8704
#define H_BYTES   (256*272)     // 69632
#define RS_SMEM   (4*A_STAGE_B + 8*B_STAGE_B + H_BYTES)   // 221184

__global__ __launch_bounds__(512, 1) void resblock_all(
        __half* __restrict__ D3, __half* __restrict__ A3,
        __half* __restrict__ D2, __half* __restrict__ D1,
        const __half* __restrict__ Wh,
        const float* __restrict__ ab_b1, const float* __restrict__ ab_b2,
        const float* __restrict__ db_b1, const float* __restrict__ db_b2) {
    extern __shared__ char smem[];
    uint32_t sA = smem_u32(smem);
    uint32_t sB = sA + 4 * A_STAGE_B;
    uint32_t sH = sB + 8 * B_STAGE_B;

    int tid = threadIdx.x;
    int wid = tid >> 5, lane = tid & 31;
    int wm = wid >> 2, wn = wid & 3;
    int g = lane >> 2, tt = lane & 3;
    int l15 = lane & 15, lhi = (lane >> 4) << 4;

    int id = blockIdx.x;
    int b = id >> 6, slot = id & 63;
    __half* X; int L, ln;
    const __half *W1, *W2; const float *b1, *b2;
    if (slot < 8)       { X = D3; L = 1024; ln = slot * 128;        W1 = Wh + 2*65536; W2 = Wh + 3*65536; b1 = db_b1; b2 = db_b2; }
    else if (slot < 16) { X = A3; L = 1024; ln = (slot - 8) * 128;  W1 = Wh + 0*65536; W2 = Wh + 1*65536; b1 = ab_b1; b2 = ab_b2; }
    else if (slot < 32) { X = D2; L = 2048; ln = (slot - 16) * 128; W1 = Wh + 2*65536; W2 = Wh + 3*65536; b1 = db_b1; b2 = db_b2; }
    else                { X = D1; L = 4096; ln = (slot - 32) * 128; W1 = Wh + 2*65536; W2 = Wh + 3*65536; b1 = db_b1; b2 = db_b2; }
    __half* Xb = X + (size_t)b * NC * L + ln;

    float acc[4][4][4];
#pragma unroll
    for (int mt = 0; mt < 4; mt++)
#pragma unroll
        for (int nt = 0; nt < 4; nt++)
#pragma unroll
            for (int r = 0; r < 4; r++) acc[mt][nt][r] = 0.f;

    auto loadAB = [&](int c, int s) {
        const __half* wsrc = (c < 8 ? W1 : W2) + (c & 7) * 32;
#pragma unroll
        for (int q = 0; q < 2; q++) {
            int idx = tid + q * 512;
            int r = idx >> 2, u = idx & 3;
            cp16(sA + s * A_STAGE_B + r * 80 + u * 16, wsrc + r * 256 + u * 8);
        }
        if (c < 8) {
            int k = tid >> 4, u = tid & 15;
            cp16(sB + c * B_STAGE_B + k * 272 + u * 16,
                 Xb + (size_t)(c * 32 + k) * L + u * 8);
        }
    };
    auto compute = [&](int c, int s) {
        uint32_t Abase = sA + s * A_STAGE_B + (wm * 64) * 80;
        uint32_t Bbase = (c < 8) ? (sB + (uint32_t)c * B_STAGE_B)
                                 : (sH + (uint32_t)(c - 8) * 32 * 272);
#pragma unroll
        for (int kk = 0; kk < 2; kk++) {
            uint32_t a[4][4];
#pragma unroll
            for (int mt = 0; mt < 4; mt++)
                ldsm4(a[mt], Abase + (mt * 16 + l15) * 80 + kk * 32 + lhi);
            uint32_t bf[2][4];
#pragma unroll
            for (int p = 0; p < 2; p++)
                ldsm4t(bf[p], Bbase + (kk * 16 + l15) * 272 + (wn * 32 + p * 16) * 2 + lhi);
#pragma unroll
            for (int mt = 0; mt < 4; mt++)
#pragma unroll
                for (int nt = 0; nt < 4; nt++)
                    mma_f16(acc[mt][nt], a[mt], &bf[nt >> 1][(nt & 1) * 2]);
        }
    };

    // prologue: chunks 0,1 in flight
    loadAB(0, 0); cp_commit();
    loadAB(1, 1); cp_commit();

#pragma unroll 1
    for (int i = 0; i < 8; i++) {
        int c0 = 2 * i;
        cp_wait0();              // all my issued groups (chunks <= c0+1) complete
        __syncthreads();         // cross-thread visibility + stage-reuse fence + H fence (i==4)
        if (c0 + 2 < 16) loadAB(c0 + 2, (c0 + 2) & 3);
        cp_commit();
        if (c0 + 3 < 16) loadAB(c0 + 3, (c0 + 3) & 3);
        cp_commit();
        compute(c0, c0 & 3);
        compute(c0 + 1, (c0 + 1) & 3);
        if (c0 == 6) {
            // GELU -> H (fp16 smem), reset acc; batch-4 barrier orders reads
#pragma unroll
            for (int mt = 0; mt < 4; mt++)
#pragma unroll
                for (int hh = 0; hh < 2; hh++) {
                    int m = wm * 64 + mt * 16 + g + hh * 8;
                    float bb = b1[m];
#pragma unroll
                    for (int nt = 0; nt < 4; nt++) {
                        float v0 = gelu_tanh(acc[mt][nt][hh * 2 + 0] + bb);
                        float v1 = gelu_tanh(acc[mt][nt][hh * 2 + 1] + bb);
                        __half2 h = __floats2half2_rn(v0, v1);
                        asm volatile("st.shared.b32 [%0], %1;"
                                     :: "r"(sH + m * 272 + (wn * 32 + nt * 8 + tt * 2) * 2),
                                        "r"(*(uint32_t*)&h));
                        acc[mt][nt][hh * 2 + 0] = 0.f;
                        acc[mt][nt][hh * 2 + 1] = 0.f;
                    }
                }
        }
    }

    // ---- epilogue: X(gmem) = X(smem-resident) + acc + b2 ----
#pragma unroll
    for (int mt = 0; mt < 4; mt++)
#pragma unroll
        for (int hh = 0; hh < 2; hh++) {
            int m = wm * 64 + mt * 16 + g + hh * 8;
            float bb = b2[m];
            size_t orow = (size_t)m * L;
            uint32_t xrow = sB + (uint32_t)(m >> 5) * B_STAGE_B + (uint32_t)(m & 31) * 272;
#pragma unroll
            for (int nt = 0; nt < 4; nt++) {
                int col = wn * 32 + nt * 8 + tt * 2;
                uint32_t xv;
                asm volatile("ld.shared.b32 %0, [%1];" : "=r"(xv) : "r"(xrow + col * 2));
                float2 rr = __half22float2(*(__half2*)&xv);
                float v0 = acc[mt][nt][hh * 2 + 0] + bb + rr.x;
                float v1 = acc[mt][nt][hh * 2 + 1] + bb + rr.y;
                *(__half2*)&Xb[orow + col] = __floats2half2_rn(v0, v1);
            }
        }
}

// ---------------- LayerNorm over channels: fp16 in, fp32 out ----------------
__global__ __launch_bounds__(256) void ln_kernel(const __half* __restrict__ S,
                                                 const float* __restrict__ g,
                                                 const float* __restrict__ bt,
                                                 float* __restrict__ out) {
    int b = blockIdx.y;
    int l0 = blockIdx.x * 128;
    int tx = threadIdx.x & 63;
    int ty = threadIdx.x >> 6;
    const __half2* Sb = (const __half2*)S;
    uint32_t r[64];
    float s0 = 0.f, s1 = 0.f, q0 = 0.f, q1 = 0.f;
#pragma unroll
    for (int q = 0; q < 64; q++) {
        int c = ty + 4 * q;
        __half2 h = Sb[(size_t)(b * NC + c) * 4096 + (l0 >> 1) + tx];
        r[q] = *(uint32_t*)&h;
        float2 f = __half22float2(h);
        s0 += f.x; s1 += f.y;
        q0 = fmaf(f.x, f.x, q0);
        q1 = fmaf(f.y, f.y, q1);
    }
    __shared__ float2 ssum[4][64], ssq[4][64];
    __shared__ float2 smu[64], srs[64];
    ssum[ty][tx] = make_float2(s0, s1);
    ssq[ty][tx] = make_float2(q0, q1);
    __syncthreads();
    if (ty == 0) {
        float2 s = ssum[0][tx], q = ssq[0][tx];
#pragma unroll
        for (int t = 1; t < 4; t++) {
            s.x += ssum[t][tx].x; s.y += ssum[t][tx].y;
            q.x += ssq[t][tx].x;  q.y += ssq[t][tx].y;
        }
        float mu0 = s.x * (1.f / NC), mu1 = s.y * (1.f / NC);
        float v0 = q.x * (1.f / NC) - mu0 * mu0;
        float v1 = q.y * (1.f / NC) - mu1 * mu1;
        smu[tx] = make_float2(mu0, mu1);
        srs[tx] = make_float2(rsqrtf(v0 + 1e-5f), rsqrtf(v1 + 1e-5f));
    }
    __syncthreads();
    float2 mu = smu[tx], rs = srs[tx];
#pragma unroll
    for (int q = 0; q < 64; q++) {
        int c = ty + 4 * q;
        __half2 h = *(__half2*)&r[q];
        float2 f = __half22float2(h);
        float gg = g[c], bbv = bt[c];
        float o0 = (f.x - mu.x) * rs.x * gg + bbv;
        float o1 = (f.y - mu.y) * rs.y * gg + bbv;
        *(float2*)&out[(size_t)(b * NC + c) * 8192 + l0 + 2 * tx] = make_float2(o0, o1);
    }
}

// ---------------- launch (single stream) ----------------
static void* sym_addr(const void* sym) {
    void* p = nullptr;
    cudaGetSymbolAddress(&p, sym);
    return p;
}

extern "C" void kernel_launch(void* const* d_in, const int* in_sizes, int n_in,
                              void* d_out, int out_size) {
    const float* x     = (const float*)d_in[0];
    const float* ab_w1 = (const float*)d_in[1];
    const float* ab_b1 = (const float*)d_in[2];
    const float* ab_w2 = (const float*)d_in[3];
    const float* ab_b2 = (const float*)d_in[4];
    const float* db_w1 = (const float*)d_in[5];
    const float* db_b1 = (const float*)d_in[6];
    const float* db_w2 = (const float*)d_in[7];
    const float* db_b2 = (const float*)d_in[8];
    const float* ln_g  = (const float*)d_in[9];
    const float* ln_b  = (const float*)d_in[10];
    float* out = (float*)d_out;

    __half* D1 = (__half*)sym_addr(g_D1);
    __half* D2 = (__half*)sym_addr(g_D2);
    __half* D3 = (__half*)sym_addr(g_D3);
    __half* A3 = (__half*)sym_addr(g_A3);
    __half* S  = (__half*)sym_addr(g_S);
    __half* Wh = (__half*)sym_addr(g_Wh);

    cudaFuncSetAttribute(resblock_all, cudaFuncAttributeMaxDynamicSharedMemorySize, RS_SMEM);
    cudaFuncSetAttribute(fused_dwt,  cudaFuncAttributeMaxDynamicSharedMemorySize, DWT_SMEM_F * 4);
    cudaFuncSetAttribute(fused_idwt, cudaFuncAttributeMaxDynamicSharedMemorySize, IDWT_SMEM_B);

    const int ROWS = NB * NC;   // 4096

    convw_kernel<<<64, 256>>>(ab_w1, ab_w2, db_w1, db_w2, Wh);

    fused_dwt<<<ROWS, 512, DWT_SMEM_F * 4>>>(x, D1, D2, D3, A3);

    resblock_all<<<1024, 512, RS_SMEM>>>(D3, A3, D2, D1, Wh,
                                         ab_b1, ab_b2, db_b1, db_b2);

    fused_idwt<<<ROWS, 512, IDWT_SMEM_B>>>(A3, D3, D2, D1, x, S);

    ln_kernel<<<dim3(8192 / 128, NB), 256>>>(S, ln_g, ln_b, out);
}

// round 13
// speedup vs baseline: 1.0148x; 1.0001x over previous
#include <cuda_runtime.h>
#include <cuda_fp16.h>
#include <cstdint>
#include <math.h>

#define NB 16
#define NC 256

// ---------------- scratch (device globals: no allocs allowed) ----------------
__device__ __half g_D1[NB*NC*4096];
__device__ __half g_D2[NB*NC*2048];
__device__ __half g_D3[NB*NC*1024];
__device__ __half g_A3[NB*NC*1024];
__device__ __half g_S [NB*NC*8192];
__device__ __half g_Wh[4*NC*NC];    // fp16 weights: ab_w1, ab_w2, db_w1, db_w2

// ---------------- db4 filters ----------------
__constant__ float c_dec_lo[8] = {-0.010597401785069032f, 0.0328830116668852f, 0.030841381835560764f, -0.18703481171888114f, -0.027983769416859854f, 0.6308807679298589f, 0.7148465705529157f, 0.2303778133088965f};
__constant__ float c_dec_hi[8] = {-0.2303778133088965f, 0.7148465705529157f, -0.6308807679298589f, -0.027983769416859854f, 0.18703481171888114f, 0.030841381835560764f, -0.0328830116668852f, -0.010597401785069032f};
__constant__ float c_rec_lo[8] = {0.2303778133088965f, 0.7148465705529157f, 0.6308807679298589f, -0.027983769416859854f, -0.18703481171888114f, 0.030841381835560764f, 0.0328830116668852f, -0.010597401785069032f};
__constant__ float c_rec_hi[8] = {-0.010597401785069032f, -0.0328830116668852f, 0.030841381835560764f, 0.18703481171888114f, -0.027983769416859854f, -0.6308807679298589f, 0.7148465705529157f, -0.2303778133088965f};

// ================= helpers =================
__device__ __forceinline__ uint32_t smem_u32(const void* p) {
    uint32_t a;
    asm("{ .reg .u64 t; cvta.to.shared.u64 t, %1; cvt.u32.u64 %0, t; }" : "=r"(a) : "l"(p));
    return a;
}
__device__ __forceinline__ void cp16(uint32_t dst, const void* src) {
    asm volatile("cp.async.cg.shared.global [%0], [%1], 16;" :: "r"(dst), "l"(src));
}
__device__ __forceinline__ void cp_commit() { asm volatile("cp.async.commit_group;" ::: "memory"); }
__device__ __forceinline__ void cp_wait2()  { asm volatile("cp.async.wait_group 2;" ::: "memory"); }

__device__ __forceinline__ void mma_f16(float* c, const uint32_t* a, const uint32_t* b) {
    asm volatile("mma.sync.aligned.m16n8k16.row.col.f32.f16.f16.f32 "
                 "{%0,%1,%2,%3}, {%4,%5,%6,%7}, {%8,%9}, {%0,%1,%2,%3};"
                 : "+f"(c[0]), "+f"(c[1]), "+f"(c[2]), "+f"(c[3])
                 : "r"(a[0]), "r"(a[1]), "r"(a[2]), "r"(a[3]), "r"(b[0]), "r"(b[1]));
}
__device__ __forceinline__ void ldsm4(uint32_t* r, uint32_t addr) {
    asm volatile("ldmatrix.sync.aligned.m8n8.x4.shared.b16 {%0,%1,%2,%3}, [%4];"
                 : "=r"(r[0]), "=r"(r[1]), "=r"(r[2]), "=r"(r[3]) : "r"(addr));
}
__device__ __forceinline__ void ldsm4t(uint32_t* r, uint32_t addr) {
    asm volatile("ldmatrix.sync.aligned.m8n8.x4.trans.shared.b16 {%0,%1,%2,%3}, [%4];"
                 : "=r"(r[0]), "=r"(r[1]), "=r"(r[2]), "=r"(r[3]) : "r"(addr));
}
__device__ __forceinline__ float gelu_tanh(float x) {
    const float k0 = 0.7978845608028654f;
    const float k1 = 0.044715f;
    float x3 = x * x * x;
    float t = tanhf(k0 * (x + k1 * x3));
    return 0.5f * x * (1.f + t);
}

// ================= fused 3-level DWT + weight conversion =================
// blocks [0, 4096): DWT rows. blocks [4096, 4160): convert one 4KB weight slice to fp16.
#define DWT_SMEM_F (2*4104 + 2*2056 + 2*1032)

__device__ __forceinline__ void dwt_level_h(const float* __restrict__ E, const float* __restrict__ O,
                                            int Lh, __half* __restrict__ dOut,
                                            float* EO, float* OO, __half* aOut) {
    for (int i = threadIdx.x; i < (Lh >> 1); i += 512) {
        int j = 2 * i;
        const float* e = E + 4 + j;
        const float* o = O + 4 + j;
        float em1 = e[-1], e0 = e[0], e1 = e[1], e2 = e[2], e3 = e[3];
        float om2 = o[-2], om1 = o[-1], o0 = o[0], o1 = o[1], o2 = o[2];
        float a0 = em1*c_dec_lo[1] + e0*c_dec_lo[3] + e1*c_dec_lo[5] + e2*c_dec_lo[7]
                 + om2*c_dec_lo[0] + om1*c_dec_lo[2] + o0*c_dec_lo[4] + o1*c_dec_lo[6];
        float a1 = e0*c_dec_lo[1] + e1*c_dec_lo[3] + e2*c_dec_lo[5] + e3*c_dec_lo[7]
                 + om1*c_dec_lo[0] + o0*c_dec_lo[2] + o1*c_dec_lo[4] + o2*c_dec_lo[6];
        float d0 = em1*c_dec_hi[1] + e0*c_dec_hi[3] + e1*c_dec_hi[5] + e2*c_dec_hi[7]
                 + om2*c_dec_hi[0] + om1*c_dec_hi[2] + o0*c_dec_hi[4] + o1*c_dec_hi[6];
        float d1 = e0*c_dec_hi[1] + e1*c_dec_hi[3] + e2*c_dec_hi[5] + e3*c_dec_hi[7]
                 + om1*c_dec_hi[0] + o0*c_dec_hi[2] + o1*c_dec_hi[4] + o2*c_dec_hi[6];
        *(__half2*)&dOut[j] = __floats2half2_rn(d0, d1);
        if (aOut) *(__half2*)&aOut[j] = __floats2half2_rn(a0, a1);
        else { EO[4 + i] = a0; OO[4 + i] = a1; }
    }
}

__global__ __launch_bounds__(512) void fused_dwt(const float* __restrict__ x,
                                                 __half* __restrict__ D1,
                                                 __half* __restrict__ D2,
                                                 __half* __restrict__ D3,
                                                 __half* __restrict__ A3,
                                                 const float* __restrict__ w0,
                                                 const float* __restrict__ w1,
                                                 const float* __restrict__ w2,
                                                 const float* __restrict__ w3,
                                                 __half* __restrict__ Wh) {
    int row = blockIdx.x, tid = threadIdx.x;

    if (row >= NB * NC) {
        // ---- weight conversion slice: 64 blocks x 512 thr, 2 float4 per thread ----
        int sl = row - NB * NC;               // 0..63, 16 per matrix
        const float* src[4] = {w0, w1, w2, w3};
        int m = sl >> 4;                       // matrix
        int off = (sl & 15) * 4096;            // float offset within matrix
        const float4* s4 = (const float4*)(src[m] + off);
        uint2* o4 = (uint2*)(Wh + m * 65536 + off);
#pragma unroll
        for (int q = 0; q < 2; q++) {
            float4 v = s4[tid + q * 512];
            __half2 h0 = __floats2half2_rn(v.x, v.y);
            __half2 h1 = __floats2half2_rn(v.z, v.w);
            o4[tid + q * 512] = make_uint2(*(uint32_t*)&h0, *(uint32_t*)&h1);
        }
        return;
    }

    extern __shared__ float sm[];
    float* E1 = sm;            // 4104
    float* O1 = sm + 4104;
    float* E2 = sm + 8208;     // 2056
    float* O2 = sm + 10264;
    float* E3 = sm + 12320;    // 1032
    float* O3 = sm + 13352;

    if (tid < 48) {            // zero pads
        int a = tid >> 3, p = tid & 7;
        float* bases[6] = {E1, O1, E2, O2, E3, O3};
        int lens[6] = {4096, 4096, 2048, 2048, 1024, 1024};
        bases[a][p < 4 ? p : lens[a] + p] = 0.f;
    }
    const float4* x4 = (const float4*)(x + (size_t)row * 8192);
    for (int i = tid; i < 2048; i += 512) {
        float4 v = x4[i];
        *(float2*)&E1[4 + 2*i] = make_float2(v.x, v.z);
        *(float2*)&O1[4 + 2*i] = make_float2(v.y, v.w);
    }
    __syncthreads();
    dwt_level_h(E1, O1, 4096, D1 + (size_t)row * 4096, E2, O2, nullptr);
    __syncthreads();
    dwt_level_h(E2, O2, 2048, D2 + (size_t)row * 2048, E3, O3, nullptr);
    __syncthreads();
    dwt_level_h(E3, O3, 1024, D3 + (size_t)row * 1024, nullptr, nullptr, A3 + (size_t)row * 1024);
}

// ================= fused 3-level IDWT + skip, quad-processed, conflict-free =================
#define IDWT_A3H 0
#define IDWT_D3H 2080
#define IDWT_D2H 4160
#define IDWT_D1H 8288
#define IDWT_Y2  16512
#define IDWT_Y1  24736
#define IDWT_SMEM_B 41152

__global__ __launch_bounds__(512) void fused_idwt(const __half* __restrict__ A3v,
                                                  const __half* __restrict__ D3v,
                                                  const __half* __restrict__ D2v,
                                                  const __half* __restrict__ D1v,
                                                  const float* __restrict__ x,
                                                  __half* __restrict__ S) {
    extern __shared__ char smc[];
    __half* A3h = (__half*)(smc + IDWT_A3H);
    __half* D3h = (__half*)(smc + IDWT_D3H);
    __half* D2h = (__half*)(smc + IDWT_D2H);
    __half* D1h = (__half*)(smc + IDWT_D1H);
    float*  Y2  = (float*)(smc + IDWT_Y2);
    float*  Y1  = (float*)(smc + IDWT_Y1);
    int row = blockIdx.x, tid = threadIdx.x;

    if (tid < 8) {
        __half* hb[4] = {A3h, D3h, D2h, D1h};
        int hl[4] = {1024, 1024, 2048, 4096};
        int a = tid >> 1, e = tid & 1;
        uint4 z = make_uint4(0, 0, 0, 0);
        *(uint4*)&hb[a][e ? 8 + hl[a] : 0] = z;
    } else if (tid < 12) {
        float* fb[2] = {Y2, Y1};
        int fl[2] = {2048, 4096};
        int a = (tid - 8) >> 1, e = tid & 1;
        *(float4*)&fb[a][e ? 4 + fl[a] : 0] = make_float4(0.f, 0.f, 0.f, 0.f);
    }
    {
        const uint4* a3 = (const uint4*)(A3v + (size_t)row * 1024);
        const uint4* d3 = (const uint4*)(D3v + (size_t)row * 1024);
        const uint4* d2 = (const uint4*)(D2v + (size_t)row * 2048);
        const uint4* d1 = (const uint4*)(D1v + (size_t)row * 4096);
        if (tid < 128)       *(uint4*)&A3h[8 + 8 * tid] = a3[tid];
        else if (tid < 256)  *(uint4*)&D3h[8 + 8 * (tid - 128)] = d3[tid - 128];
        else                 *(uint4*)&D2h[8 + 8 * (tid - 256)] = d2[tid - 256];
        *(uint4*)&D1h[8 + 8 * tid] = d1[tid];
    }
    __syncthreads();

    {
        int i = tid;
        float2 am = __half22float2(*(const __half2*)&A3h[6 + 2*i]);
        float2 ac = __half22float2(*(const __half2*)&A3h[8 + 2*i]);
        float2 ap = __half22float2(*(const __half2*)&A3h[10 + 2*i]);
        float2 dm = __half22float2(*(const __half2*)&D3h[6 + 2*i]);
        float2 dc = __half22float2(*(const __half2*)&D3h[8 + 2*i]);
        float2 dp = __half22float2(*(const __half2*)&D3h[10 + 2*i]);
        float y0 = am.x*c_rec_lo[7] + am.y*c_rec_lo[5] + ac.x*c_rec_lo[3] + ac.y*c_rec_lo[1]
                 + dm.x*c_rec_hi[7] + dm.y*c_rec_hi[5] + dc.x*c_rec_hi[3] + dc.y*c_rec_hi[1];
        float y1 = am.y*c_rec_lo[6] + ac.x*c_rec_lo[4] + ac.y*c_rec_lo[2] + ap.x*c_rec_lo[0]
                 + dm.y*c_rec_hi[6] + dc.x*c_rec_hi[4] + dc.y*c_rec_hi[2] + dp.x*c_rec_hi[0];
        float y2 = am.y*c_rec_lo[7] + ac.x*c_rec_lo[5] + ac.y*c_rec_lo[3] + ap.x*c_rec_lo[1]
                 + dm.y*c_rec_hi[7] + dc.x*c_rec_hi[5] + dc.y*c_rec_hi[3] + dp.x*c_rec_hi[1];
        float y3 = ac.x*c_rec_lo[6] + ac.y*c_rec_lo[4] + ap.x*c_rec_lo[2] + ap.y*c_rec_lo[0]
                 + dc.x*c_rec_hi[6] + dc.y*c_rec_hi[4] + dp.x*c_rec_hi[2] + dp.y*c_rec_hi[0];
        *(float4*)&Y2[4 + 4*i] = make_float4(y0, y1, y2, y3);
    }
    __syncthreads();

#pragma unroll
    for (int q = 0; q < 2; q++) {
        int i = tid + q * 512;
        float2 am = *(const float2*)&Y2[2 + 2*i];
        float2 ac = *(const float2*)&Y2[4 + 2*i];
        float2 ap = *(const float2*)&Y2[6 + 2*i];
        float2 dm = __half22float2(*(const __half2*)&D2h[6 + 2*i]);
        float2 dc = __half22float2(*(const __half2*)&D2h[8 + 2*i]);
        float2 dp = __half22float2(*(const __half2*)&D2h[10 + 2*i]);
        float y0 = am.x*c_rec_lo[7] + am.y*c_rec_lo[5] + ac.x*c_rec_lo[3] + ac.y*c_rec_lo[1]
                 + dm.x*c_rec_hi[7] + dm.y*c_rec_hi[5] + dc.x*c_rec_hi[3] + dc.y*c_rec_hi[1];
        float y1 = am.y*c_rec_lo[6] + ac.x*c_rec_lo[4] + ac.y*c_rec_lo[2] + ap.x*c_rec_lo[0]
                 + dm.y*c_rec_hi[6] + dc.x*c_rec_hi[4] + dc.y*c_rec_hi[2] + dp.x*c_rec_hi[0];
        float y2 = am.y*c_rec_lo[7] + ac.x*c_rec_lo[5] + ac.y*c_rec_lo[3] + ap.x*c_rec_lo[1]
                 + dm.y*c_rec_hi[7] + dc.x*c_rec_hi[5] + dc.y*c_rec_hi[3] + dp.x*c_rec_hi[1];
        float y3 = ac.x*c_rec_lo[6] + ac.y*c_rec_lo[4] + ap.x*c_rec_lo[2] + ap.y*c_rec_lo[0]
                 + dc.x*c_rec_hi[6] + dc.y*c_rec_hi[4] + dp.x*c_rec_hi[2] + dp.y*c_rec_hi[0];
        *(float4*)&Y1[4 + 4*i] = make_float4(y0, y1, y2, y3);
    }
    __syncthreads();

    const float* xr = x + (size_t)row * 8192;
    __half* Sr = S + (size_t)row * 8192;
#pragma unroll
    for (int q = 0; q < 4; q++) {
        int i = tid + q * 512;
        float2 am = *(const float2*)&Y1[2 + 2*i];
        float2 ac = *(const float2*)&Y1[4 + 2*i];
        float2 ap = *(const float2*)&Y1[6 + 2*i];
        float2 dm = __half22float2(*(const __half2*)&D1h[6 + 2*i]);
        float2 dc = __half22float2(*(const __half2*)&D1h[8 + 2*i]);
        float2 dp = __half22float2(*(const __half2*)&D1h[10 + 2*i]);
        float y0 = am.x*c_rec_lo[7] + am.y*c_rec_lo[5] + ac.x*c_rec_lo[3] + ac.y*c_rec_lo[1]
                 + dm.x*c_rec_hi[7] + dm.y*c_rec_hi[5] + dc.x*c_rec_hi[3] + dc.y*c_rec_hi[1];
        float y1 = am.y*c_rec_lo[6] + ac.x*c_rec_lo[4] + ac.y*c_rec_lo[2] + ap.x*c_rec_lo[0]
                 + dm.y*c_rec_hi[6] + dc.x*c_rec_hi[4] + dc.y*c_rec_hi[2] + dp.x*c_rec_hi[0];
        float y2 = am.y*c_rec_lo[7] + ac.x*c_rec_lo[5] + ac.y*c_rec_lo[3] + ap.x*c_rec_lo[1]
                 + dm.y*c_rec_hi[7] + dc.x*c_rec_hi[5] + dc.y*c_rec_hi[3] + dp.x*c_rec_hi[1];
        float y3 = ac.x*c_rec_lo[6] + ac.y*c_rec_lo[4] + ap.x*c_rec_lo[2] + ap.y*c_rec_lo[0]
                 + dc.x*c_rec_hi[6] + dc.y*c_rec_hi[4] + dp.x*c_rec_hi[2] + dp.y*c_rec_hi[0];
        float4 xv = *(const float4*)&xr[4*i];
        __half2 h0 = __floats2half2_rn(y0 + xv.x, y1 + xv.y);
        __half2 h1 = __floats2half2_rn(y2 + xv.z, y3 + xv.w);
        uint2 pk = make_uint2(*(uint32_t*)&h0, *(uint32_t*)&h1);
        *(uint2*)&Sr[4*i] = pk;
    }
}

// ================= combined fused res blocks (round-8 structure, best measured) =================
#define A_STAGE_B (256*80)      // 20480
#define B_STAGE_B (32*272)      // 8704
#define H_BYTES   (256*272)     // 69632
#define RS_SMEM   (4*A_STAGE_B + 8*B_STAGE_B + H_BYTES)   // 221184

__global__ __launch_bounds__(512, 1) void resblock_all(
        __half* __restrict__ D3, __half* __restrict__ A3,
        __half* __restrict__ D2, __half* __restrict__ D1,
        const __half* __restrict__ Wh,
        const float* __restrict__ ab_b1, const float* __restrict__ ab_b2,
        const float* __restrict__ db_b1, const float* __restrict__ db_b2) {
    extern __shared__ char smem[];
    uint32_t sA = smem_u32(smem);
    uint32_t sB = sA + 4 * A_STAGE_B;
    uint32_t sH = sB + 8 * B_STAGE_B;

    int tid = threadIdx.x;
    int wid = tid >> 5, lane = tid & 31;
    int wm = wid >> 2, wn = wid & 3;
    int g = lane >> 2, tt = lane & 3;
    int l15 = lane & 15, lhi = (lane >> 4) << 4;

    int id = blockIdx.x;
    int b = id >> 6, slot = id & 63;
    __half* X; int L, ln;
    const __half *W1, *W2; const float *b1, *b2;
    if (slot < 8)       { X = D3; L = 1024; ln = slot * 128;        W1 = Wh + 2*65536; W2 = Wh + 3*65536; b1 = db_b1; b2 = db_b2; }
    else if (slot < 16) { X = A3; L = 1024; ln = (slot - 8) * 128;  W1 = Wh + 0*65536; W2 = Wh + 1*65536; b1 = ab_b1; b2 = ab_b2; }
    else if (slot < 32) { X = D2; L = 2048; ln = (slot - 16) * 128; W1 = Wh + 2*65536; W2 = Wh + 3*65536; b1 = db_b1; b2 = db_b2; }
    else                { X = D1; L = 4096; ln = (slot - 32) * 128; W1 = Wh + 2*65536; W2 = Wh + 3*65536; b1 = db_b1; b2 = db_b2; }
    __half* Xb = X + (size_t)b * NC * L + ln;

    float acc[4][4][4];
#pragma unroll
    for (int mt = 0; mt < 4; mt++)
#pragma unroll
        for (int nt = 0; nt < 4; nt++)
#pragma unroll
            for (int r = 0; r < 4; r++) acc[mt][nt][r] = 0.f;

    auto loadAB = [&](int c, int s) {
        const __half* wsrc = (c < 8 ? W1 : W2) + (c & 7) * 32;
#pragma unroll
        for (int q = 0; q < 2; q++) {
            int idx = tid + q * 512;
            int r = idx >> 2, u = idx & 3;
            cp16(sA + s * A_STAGE_B + r * 80 + u * 16, wsrc + r * 256 + u * 8);
        }
        if (c < 8) {
            int k = tid >> 4, u = tid & 15;
            cp16(sB + c * B_STAGE_B + k * 272 + u * 16,
                 Xb + (size_t)(c * 32 + k) * L + u * 8);
        }
    };
    auto compute = [&](int c, int s) {
        uint32_t Abase = sA + s * A_STAGE_B + (wm * 64) * 80;
        uint32_t Bbase = (c < 8) ? (sB + (uint32_t)c * B_STAGE_B)
                                 : (sH + (uint32_t)(c - 8) * 32 * 272);
#pragma unroll
        for (int kk = 0; kk < 2; kk++) {
            uint32_t a[4][4];
#pragma unroll
            for (int mt = 0; mt < 4; mt++)
                ldsm4(a[mt], Abase + (mt * 16 + l15) * 80 + kk * 32 + lhi);
            uint32_t bf[2][4];
#pragma unroll
            for (int p = 0; p < 2; p++)
                ldsm4t(bf[p], Bbase + (kk * 16 + l15) * 272 + (wn * 32 + p * 16) * 2 + lhi);
#pragma unroll
            for (int mt = 0; mt < 4; mt++)
#pragma unroll
                for (int nt = 0; nt < 4; nt++)
                    mma_f16(acc[mt][nt], a[mt], &bf[nt >> 1][(nt & 1) * 2]);
        }
    };

    loadAB(0, 0); cp_commit();
    loadAB(1, 1); cp_commit();
    loadAB(2, 2); cp_commit();

#pragma unroll 1
    for (int c = 0; c < 16; c++) {
        int s = c & 3;
        cp_wait2();
        __syncthreads();
        if (c + 3 < 16) loadAB(c + 3, (c + 3) & 3);
        cp_commit();
        compute(c, s);
        if (c == 7) {
#pragma unroll
            for (int mt = 0; mt < 4; mt++)
#pragma unroll
                for (int hh = 0; hh < 2; hh++) {
                    int m = wm * 64 + mt * 16 + g + hh * 8;
                    float bb = b1[m];
#pragma unroll
                    for (int nt = 0; nt < 4; nt++) {
                        float v0 = gelu_tanh(acc[mt][nt][hh * 2 + 0] + bb);
                        float v1 = gelu_tanh(acc[mt][nt][hh * 2 + 1] + bb);
                        __half2 h = __floats2half2_rn(v0, v1);
                        asm volatile("st.shared.b32 [%0], %1;"
                                     :: "r"(sH + m * 272 + (wn * 32 + nt * 8 + tt * 2) * 2),
                                        "r"(*(uint32_t*)&h));
                        acc[mt][nt][hh * 2 + 0] = 0.f;
                        acc[mt][nt][hh * 2 + 1] = 0.f;
                    }
                }
        }
    }

    // ---- epilogue: X(gmem) = X(smem-resident) + acc + b2 ----
#pragma unroll
    for (int mt = 0; mt < 4; mt++)
#pragma unroll
        for (int hh = 0; hh < 2; hh++) {
            int m = wm * 64 + mt * 16 + g + hh * 8;
            float bb = b2[m];
            size_t orow = (size_t)m * L;
            uint32_t xrow = sB + (uint32_t)(m >> 5) * B_STAGE_B + (uint32_t)(m & 31) * 272;
#pragma unroll
            for (int nt = 0; nt < 4; nt++) {
                int col = wn * 32 + nt * 8 + tt * 2;
                uint32_t xv;
                asm volatile("ld.shared.b32 %0, [%1];" : "=r"(xv) : "r"(xrow + col * 2));
                float2 rr = __half22float2(*(__half2*)&xv);
                float v0 = acc[mt][nt][hh * 2 + 0] + bb + rr.x;
                float v1 = acc[mt][nt][hh * 2 + 1] + bb + rr.y;
                *(__half2*)&Xb[orow + col] = __floats2half2_rn(v0, v1);
            }
        }
}

// ---------------- LayerNorm over channels: fp16 in, fp32 out ----------------
__global__ __launch_bounds__(256) void ln_kernel(const __half* __restrict__ S,
                                                 const float* __restrict__ g,
                                                 const float* __restrict__ bt,
                                                 float* __restrict__ out) {
    int b = blockIdx.y;
    int l0 = blockIdx.x * 128;
    int tx = threadIdx.x & 63;
    int ty = threadIdx.x >> 6;
    const __half2* Sb = (const __half2*)S;
    uint32_t r[64];
    float s0 = 0.f, s1 = 0.f, q0 = 0.f, q1 = 0.f;
#pragma unroll
    for (int q = 0; q < 64; q++) {
        int c = ty + 4 * q;
        __half2 h = Sb[(size_t)(b * NC + c) * 4096 + (l0 >> 1) + tx];
        r[q] = *(uint32_t*)&h;
        float2 f = __half22float2(h);
        s0 += f.x; s1 += f.y;
        q0 = fmaf(f.x, f.x, q0);
        q1 = fmaf(f.y, f.y, q1);
    }
    __shared__ float2 ssum[4][64], ssq[4][64];
    __shared__ float2 smu[64], srs[64];
    ssum[ty][tx] = make_float2(s0, s1);
    ssq[ty][tx] = make_float2(q0, q1);
    __syncthreads();
    if (ty == 0) {
        float2 s = ssum[0][tx], q = ssq[0][tx];
#pragma unroll
        for (int t = 1; t < 4; t++) {
            s.x += ssum[t][tx].x; s.y += ssum[t][tx].y;
            q.x += ssq[t][tx].x;  q.y += ssq[t][tx].y;
        }
        float mu0 = s.x * (1.f / NC), mu1 = s.y * (1.f / NC);
        float v0 = q.x * (1.f / NC) - mu0 * mu0;
        float v1 = q.y * (1.f / NC) - mu1 * mu1;
        smu[tx] = make_float2(mu0, mu1);
        srs[tx] = make_float2(rsqrtf(v0 + 1e-5f), rsqrtf(v1 + 1e-5f));
    }
    __syncthreads();
    float2 mu = smu[tx], rs = srs[tx];
#pragma unroll
    for (int q = 0; q < 64; q++) {
        int c = ty + 4 * q;
        __half2 h = *(__half2*)&r[q];
        float2 f = __half22float2(h);
        float gg = g[c], bbv = bt[c];
        float o0 = (f.x - mu.x) * rs.x * gg + bbv;
        float o1 = (f.y - mu.y) * rs.y * gg + bbv;
        *(float2*)&out[(size_t)(b * NC + c) * 8192 + l0 + 2 * tx] = make_float2(o0, o1);
    }
}

// ---------------- launch (single stream) ----------------
static void* sym_addr(const void* sym) {
    void* p = nullptr;
    cudaGetSymbolAddress(&p, sym);
    return p;
}

extern "C" void kernel_launch(void* const* d_in, const int* in_sizes, int n_in,
                              void* d_out, int out_size) {
    const float* x     = (const float*)d_in[0];
    const float* ab_w1 = (const float*)d_in[1];
    const float* ab_b1 = (const float*)d_in[2];
    const float* ab_w2 = (const float*)d_in[3];
    const float* ab_b2 = (const float*)d_in[4];
    const float* db_w1 = (const float*)d_in[5];
    const float* db_b1 = (const float*)d_in[6];
    const float* db_w2 = (const float*)d_in[7];
    const float* db_b2 = (const float*)d_in[8];
    const float* ln_g  = (const float*)d_in[9];
    const float* ln_b  = (const float*)d_in[10];
    float* out = (float*)d_out;

    __half* D1 = (__half*)sym_addr(g_D1);
    __half* D2 = (__half*)sym_addr(g_D2);
    __half* D3 = (__half*)sym_addr(g_D3);
    __half* A3 = (__half*)sym_addr(g_A3);
    __half* S  = (__half*)sym_addr(g_S);
    __half* Wh = (__half*)sym_addr(g_Wh);

    cudaFuncSetAttribute(resblock_all, cudaFuncAttributeMaxDynamicSharedMemorySize, RS_SMEM);
    cudaFuncSetAttribute(fused_dwt,  cudaFuncAttributeMaxDynamicSharedMemorySize, DWT_SMEM_F * 4);
    cudaFuncSetAttribute(fused_idwt, cudaFuncAttributeMaxDynamicSharedMemorySize, IDWT_SMEM_B);

    const int ROWS = NB * NC;   // 4096

    // fused forward DWT + weight conversion (64 extra blocks)
    fused_dwt<<<ROWS + 64, 512, DWT_SMEM_F * 4>>>(x, D1, D2, D3, A3,
                                                  ab_w1, ab_w2, db_w1, db_w2, Wh);

    resblock_all<<<1024, 512, RS_SMEM>>>(D3, A3, D2, D1, Wh,
                                         ab_b1, ab_b2, db_b1, db_b2);

    fused_idwt<<<ROWS, 512, IDWT_SMEM_B>>>(A3, D3, D2, D1, x, S);

    ln_kernel<<<dim3(8192 / 128, NB), 256>>>(S, ln_g, ln_b, out);
}

// round 14
// speedup vs baseline: 1.0290x; 1.0140x over previous
#include <cuda_runtime.h>
#include <cuda_fp16.h>
#include <cstdint>
#include <math.h>

#define NB 16
#define NC 256

// ---------------- scratch (device globals: no allocs allowed) ----------------
__device__ __half g_D1[NB*NC*4096];
__device__ __half g_D2[NB*NC*2048];
__device__ __half g_D3[NB*NC*1024];
__device__ __half g_A3[NB*NC*1024];
__device__ __half g_S [NB*NC*8192];
__device__ __half g_Wh[4*NC*NC];    // fp16 weights: ab_w1, ab_w2, db_w1, db_w2

// ---------------- db4 filters ----------------
__constant__ float c_dec_lo[8] = {-0.010597401785069032f, 0.0328830116668852f, 0.030841381835560764f, -0.18703481171888114f, -0.027983769416859854f, 0.6308807679298589f, 0.7148465705529157f, 0.2303778133088965f};
__constant__ float c_dec_hi[8] = {-0.2303778133088965f, 0.7148465705529157f, -0.6308807679298589f, -0.027983769416859854f, 0.18703481171888114f, 0.030841381835560764f, -0.0328830116668852f, -0.010597401785069032f};
__constant__ float c_rec_lo[8] = {0.2303778133088965f, 0.7148465705529157f, 0.6308807679298589f, -0.027983769416859854f, -0.18703481171888114f, 0.030841381835560764f, 0.0328830116668852f, -0.010597401785069032f};
__constant__ float c_rec_hi[8] = {-0.010597401785069032f, -0.0328830116668852f, 0.030841381835560764f, 0.18703481171888114f, -0.027983769416859854f, -0.6308807679298589f, 0.7148465705529157f, -0.2303778133088965f};

// ================= helpers =================
__device__ __forceinline__ uint32_t smem_u32(const void* p) {
    uint32_t a;
    asm("{ .reg .u64 t; cvta.to.shared.u64 t, %1; cvt.u32.u64 %0, t; }" : "=r"(a) : "l"(p));
    return a;
}
__device__ __forceinline__ void cp16(uint32_t dst, const void* src) {
    asm volatile("cp.async.cg.shared.global [%0], [%1], 16;" :: "r"(dst), "l"(src));
}
__device__ __forceinline__ void cp_commit() { asm volatile("cp.async.commit_group;" ::: "memory"); }
__device__ __forceinline__ void cp_wait2()  { asm volatile("cp.async.wait_group 2;" ::: "memory"); }

__device__ __forceinline__ void mma_f16(float* c, const uint32_t* a, const uint32_t* b) {
    asm volatile("mma.sync.aligned.m16n8k16.row.col.f32.f16.f16.f32 "
                 "{%0,%1,%2,%3}, {%4,%5,%6,%7}, {%8,%9}, {%0,%1,%2,%3};"
                 : "+f"(c[0]), "+f"(c[1]), "+f"(c[2]), "+f"(c[3])
                 : "r"(a[0]), "r"(a[1]), "r"(a[2]), "r"(a[3]), "r"(b[0]), "r"(b[1]));
}
__device__ __forceinline__ void ldsm4(uint32_t* r, uint32_t addr) {
    asm volatile("ldmatrix.sync.aligned.m8n8.x4.shared.b16 {%0,%1,%2,%3}, [%4];"
                 : "=r"(r[0]), "=r"(r[1]), "=r"(r[2]), "=r"(r[3]) : "r"(addr));
}
__device__ __forceinline__ void ldsm4t(uint32_t* r, uint32_t addr) {
    asm volatile("ldmatrix.sync.aligned.m8n8.x4.trans.shared.b16 {%0,%1,%2,%3}, [%4];"
                 : "=r"(r[0]), "=r"(r[1]), "=r"(r[2]), "=r"(r[3]) : "r"(addr));
}
__device__ __forceinline__ float gelu_tanh(float x) {
    const float k0 = 0.7978845608028654f;
    const float k1 = 0.044715f;
    float x3 = x * x * x;
    float t = tanhf(k0 * (x + k1 * x3));
    return 0.5f * x * (1.f + t);
}

// ================= fused 3-level DWT + weight conversion =================
#define DWT_SMEM_F (2*4104 + 2*2056 + 2*1032)

__device__ __forceinline__ void dwt_level_h(const float* __restrict__ E, const float* __restrict__ O,
                                            int Lh, __half* __restrict__ dOut,
                                            float* EO, float* OO, __half* aOut) {
    for (int i = threadIdx.x; i < (Lh >> 1); i += 512) {
        int j = 2 * i;
        const float* e = E + 4 + j;
        const float* o = O + 4 + j;
        float em1 = e[-1], e0 = e[0], e1 = e[1], e2 = e[2], e3 = e[3];
        float om2 = o[-2], om1 = o[-1], o0 = o[0], o1 = o[1], o2 = o[2];
        float a0 = em1*c_dec_lo[1] + e0*c_dec_lo[3] + e1*c_dec_lo[5] + e2*c_dec_lo[7]
                 + om2*c_dec_lo[0] + om1*c_dec_lo[2] + o0*c_dec_lo[4] + o1*c_dec_lo[6];
        float a1 = e0*c_dec_lo[1] + e1*c_dec_lo[3] + e2*c_dec_lo[5] + e3*c_dec_lo[7]
                 + om1*c_dec_lo[0] + o0*c_dec_lo[2] + o1*c_dec_lo[4] + o2*c_dec_lo[6];
        float d0 = em1*c_dec_hi[1] + e0*c_dec_hi[3] + e1*c_dec_hi[5] + e2*c_dec_hi[7]
                 + om2*c_dec_hi[0] + om1*c_dec_hi[2] + o0*c_dec_hi[4] + o1*c_dec_hi[6];
        float d1 = e0*c_dec_hi[1] + e1*c_dec_hi[3] + e2*c_dec_hi[5] + e3*c_dec_hi[7]
                 + om1*c_dec_hi[0] + o0*c_dec_hi[2] + o1*c_dec_hi[4] + o2*c_dec_hi[6];
        *(__half2*)&dOut[j] = __floats2half2_rn(d0, d1);
        if (aOut) *(__half2*)&aOut[j] = __floats2half2_rn(a0, a1);
        else { EO[4 + i] = a0; OO[4 + i] = a1; }
    }
}

__global__ __launch_bounds__(512) void fused_dwt(const float* __restrict__ x,
                                                 __half* __restrict__ D1,
                                                 __half* __restrict__ D2,
                                                 __half* __restrict__ D3,
                                                 __half* __restrict__ A3,
                                                 const float* __restrict__ w0,
                                                 const float* __restrict__ w1,
                                                 const float* __restrict__ w2,
                                                 const float* __restrict__ w3,
                                                 __half* __restrict__ Wh) {
    int row = blockIdx.x, tid = threadIdx.x;

    if (row >= NB * NC) {
        // ---- weight conversion slice ----
        int sl = row - NB * NC;
        const float* src[4] = {w0, w1, w2, w3};
        int m = sl >> 4;
        int off = (sl & 15) * 4096;
        const float4* s4 = (const float4*)(src[m] + off);
        uint2* o4 = (uint2*)(Wh + m * 65536 + off);
#pragma unroll
        for (int q = 0; q < 2; q++) {
            float4 v = s4[tid + q * 512];
            __half2 h0 = __floats2half2_rn(v.x, v.y);
            __half2 h1 = __floats2half2_rn(v.z, v.w);
            o4[tid + q * 512] = make_uint2(*(uint32_t*)&h0, *(uint32_t*)&h1);
        }
        return;
    }

    extern __shared__ float sm[];
    float* E1 = sm;
    float* O1 = sm + 4104;
    float* E2 = sm + 8208;
    float* O2 = sm + 10264;
    float* E3 = sm + 12320;
    float* O3 = sm + 13352;

    if (tid < 48) {
        int a = tid >> 3, p = tid & 7;
        float* bases[6] = {E1, O1, E2, O2, E3, O3};
        int lens[6] = {4096, 4096, 2048, 2048, 1024, 1024};
        bases[a][p < 4 ? p : lens[a] + p] = 0.f;
    }
    const float4* x4 = (const float4*)(x + (size_t)row * 8192);
    for (int i = tid; i < 2048; i += 512) {
        float4 v = x4[i];
        *(float2*)&E1[4 + 2*i] = make_float2(v.x, v.z);
        *(float2*)&O1[4 + 2*i] = make_float2(v.y, v.w);
    }
    __syncthreads();
    dwt_level_h(E1, O1, 4096, D1 + (size_t)row * 4096, E2, O2, nullptr);
    __syncthreads();
    dwt_level_h(E2, O2, 2048, D2 + (size_t)row * 2048, E3, O3, nullptr);
    __syncthreads();
    dwt_level_h(E3, O3, 1024, D3 + (size_t)row * 1024, nullptr, nullptr, A3 + (size_t)row * 1024);
}

// ================= fused 3-level IDWT + skip, quad-processed, conflict-free =================
#define IDWT_A3H 0
#define IDWT_D3H 2080
#define IDWT_D2H 4160
#define IDWT_D1H 8288
#define IDWT_Y2  16512
#define IDWT_Y1  24736
#define IDWT_SMEM_B 41152

__global__ __launch_bounds__(512) void fused_idwt(const __half* __restrict__ A3v,
                                                  const __half* __restrict__ D3v,
                                                  const __half* __restrict__ D2v,
                                                  const __half* __restrict__ D1v,
                                                  const float* __restrict__ x,
                                                  __half* __restrict__ S) {
    extern __shared__ char smc[];
    __half* A3h = (__half*)(smc + IDWT_A3H);
    __half* D3h = (__half*)(smc + IDWT_D3H);
    __half* D2h = (__half*)(smc + IDWT_D2H);
    __half* D1h = (__half*)(smc + IDWT_D1H);
    float*  Y2  = (float*)(smc + IDWT_Y2);
    float*  Y1  = (float*)(smc + IDWT_Y1);
    int row = blockIdx.x, tid = threadIdx.x;

    if (tid < 8) {
        __half* hb[4] = {A3h, D3h, D2h, D1h};
        int hl[4] = {1024, 1024, 2048, 4096};
        int a = tid >> 1, e = tid & 1;
        uint4 z = make_uint4(0, 0, 0, 0);
        *(uint4*)&hb[a][e ? 8 + hl[a] : 0] = z;
    } else if (tid < 12) {
        float* fb[2] = {Y2, Y1};
        int fl[2] = {2048, 4096};
        int a = (tid - 8) >> 1, e = tid & 1;
        *(float4*)&fb[a][e ? 4 + fl[a] : 0] = make_float4(0.f, 0.f, 0.f, 0.f);
    }
    {
        const uint4* a3 = (const uint4*)(A3v + (size_t)row * 1024);
        const uint4* d3 = (const uint4*)(D3v + (size_t)row * 1024);
        const uint4* d2 = (const uint4*)(D2v + (size_t)row * 2048);
        const uint4* d1 = (const uint4*)(D1v + (size_t)row * 4096);
        if (tid < 128)       *(uint4*)&A3h[8 + 8 * tid] = a3[tid];
        else if (tid < 256)  *(uint4*)&D3h[8 + 8 * (tid - 128)] = d3[tid - 128];
        else                 *(uint4*)&D2h[8 + 8 * (tid - 256)] = d2[tid - 256];
        *(uint4*)&D1h[8 + 8 * tid] = d1[tid];
    }
    __syncthreads();

    {
        int i = tid;
        float2 am = __half22float2(*(const __half2*)&A3h[6 + 2*i]);
        float2 ac = __half22float2(*(const __half2*)&A3h[8 + 2*i]);
        float2 ap = __half22float2(*(const __half2*)&A3h[10 + 2*i]);
        float2 dm = __half22float2(*(const __half2*)&D3h[6 + 2*i]);
        float2 dc = __half22float2(*(const __half2*)&D3h[8 + 2*i]);
        float2 dp = __half22float2(*(const __half2*)&D3h[10 + 2*i]);
        float y0 = am.x*c_rec_lo[7] + am.y*c_rec_lo[5] + ac.x*c_rec_lo[3] + ac.y*c_rec_lo[1]
                 + dm.x*c_rec_hi[7] + dm.y*c_rec_hi[5] + dc.x*c_rec_hi[3] + dc.y*c_rec_hi[1];
        float y1 = am.y*c_rec_lo[6] + ac.x*c_rec_lo[4] + ac.y*c_rec_lo[2] + ap.x*c_rec_lo[0]
                 + dm.y*c_rec_hi[6] + dc.x*c_rec_hi[4] + dc.y*c_rec_hi[2] + dp.x*c_rec_hi[0];
        float y2 = am.y*c_rec_lo[7] + ac.x*c_rec_lo[5] + ac.y*c_rec_lo[3] + ap.x*c_rec_lo[1]
                 + dm.y*c_rec_hi[7] + dc.x*c_rec_hi[5] + dc.y*c_rec_hi[3] + dp.x*c_rec_hi[1];
        float y3 = ac.x*c_rec_lo[6] + ac.y*c_rec_lo[4] + ap.x*c_rec_lo[2] + ap.y*c_rec_lo[0]
                 + dc.x*c_rec_hi[6] + dc.y*c_rec_hi[4] + dp.x*c_rec_hi[2] + dp.y*c_rec_hi[0];
        *(float4*)&Y2[4 + 4*i] = make_float4(y0, y1, y2, y3);
    }
    __syncthreads();

#pragma unroll
    for (int q = 0; q < 2; q++) {
        int i = tid + q * 512;
        float2 am = *(const float2*)&Y2[2 + 2*i];
        float2 ac = *(const float2*)&Y2[4 + 2*i];
        float2 ap = *(const float2*)&Y2[6 + 2*i];
        float2 dm = __half22float2(*(const __half2*)&D2h[6 + 2*i]);
        float2 dc = __half22float2(*(const __half2*)&D2h[8 + 2*i]);
        float2 dp = __half22float2(*(const __half2*)&D2h[10 + 2*i]);
        float y0 = am.x*c_rec_lo[7] + am.y*c_rec_lo[5] + ac.x*c_rec_lo[3] + ac.y*c_rec_lo[1]
                 + dm.x*c_rec_hi[7] + dm.y*c_rec_hi[5] + dc.x*c_rec_hi[3] + dc.y*c_rec_hi[1];
        float y1 = am.y*c_rec_lo[6] + ac.x*c_rec_lo[4] + ac.y*c_rec_lo[2] + ap.x*c_rec_lo[0]
                 + dm.y*c_rec_hi[6] + dc.x*c_rec_hi[4] + dc.y*c_rec_hi[2] + dp.x*c_rec_hi[0];
        float y2 = am.y*c_rec_lo[7] + ac.x*c_rec_lo[5] + ac.y*c_rec_lo[3] + ap.x*c_rec_lo[1]
                 + dm.y*c_rec_hi[7] + dc.x*c_rec_hi[5] + dc.y*c_rec_hi[3] + dp.x*c_rec_hi[1];
        float y3 = ac.x*c_rec_lo[6] + ac.y*c_rec_lo[4] + ap.x*c_rec_lo[2] + ap.y*c_rec_lo[0]
                 + dc.x*c_rec_hi[6] + dc.y*c_rec_hi[4] + dp.x*c_rec_hi[2] + dp.y*c_rec_hi[0];
        *(float4*)&Y1[4 + 4*i] = make_float4(y0, y1, y2, y3);
    }
    __syncthreads();

    const float* xr = x + (size_t)row * 8192;
    __half* Sr = S + (size_t)row * 8192;
#pragma unroll
    for (int q = 0; q < 4; q++) {
        int i = tid + q * 512;
        float2 am = *(const float2*)&Y1[2 + 2*i];
        float2 ac = *(const float2*)&Y1[4 + 2*i];
        float2 ap = *(const float2*)&Y1[6 + 2*i];
        float2 dm = __half22float2(*(const __half2*)&D1h[6 + 2*i]);
        float2 dc = __half22float2(*(const __half2*)&D1h[8 + 2*i]);
        float2 dp = __half22float2(*(const __half2*)&D1h[10 + 2*i]);
        float y0 = am.x*c_rec_lo[7] + am.y*c_rec_lo[5] + ac.x*c_rec_lo[3] + ac.y*c_rec_lo[1]
                 + dm.x*c_rec_hi[7] + dm.y*c_rec_hi[5] + dc.x*c_rec_hi[3] + dc.y*c_rec_hi[1];
        float y1 = am.y*c_rec_lo[6] + ac.x*c_rec_lo[4] + ac.y*c_rec_lo[2] + ap.x*c_rec_lo[0]
                 + dm.y*c_rec_hi[6] + dc.x*c_rec_hi[4] + dc.y*c_rec_hi[2] + dp.x*c_rec_hi[0];
        float y2 = am.y*c_rec_lo[7] + ac.x*c_rec_lo[5] + ac.y*c_rec_lo[3] + ap.x*c_rec_lo[1]
                 + dm.y*c_rec_hi[7] + dc.x*c_rec_hi[5] + dc.y*c_rec_hi[3] + dp.x*c_rec_hi[1];
        float y3 = ac.x*c_rec_lo[6] + ac.y*c_rec_lo[4] + ap.x*c_rec_lo[2] + ap.y*c_rec_lo[0]
                 + dc.x*c_rec_hi[6] + dc.y*c_rec_hi[4] + dp.x*c_rec_hi[2] + dp.y*c_rec_hi[0];
        float4 xv = *(const float4*)&xr[4*i];
        __half2 h0 = __floats2half2_rn(y0 + xv.x, y1 + xv.y);
        __half2 h1 = __floats2half2_rn(y2 + xv.z, y3 + xv.w);
        uint2 pk = make_uint2(*(uint32_t*)&h0, *(uint32_t*)&h1);
        *(uint2*)&Sr[4*i] = pk;
    }
}

// ================= combined fused res blocks (round-8 structure, best measured) =================
#define A_STAGE_B (256*80)      // 20480
#define B_STAGE_B (32*272)      // 8704
#define H_BYTES   (256*272)     // 69632
#define RS_SMEM   (4*A_STAGE_B + 8*B_STAGE_B + H_BYTES)   // 221184

__global__ __launch_bounds__(512, 1) void resblock_all(
        __half* __restrict__ D3, __half* __restrict__ A3,
        __half* __restrict__ D2, __half* __restrict__ D1,
        const __half* __restrict__ Wh,
        const float* __restrict__ ab_b1, const float* __restrict__ ab_b2,
        const float* __restrict__ db_b1, const float* __restrict__ db_b2) {
    extern __shared__ char smem[];
    uint32_t sA = smem_u32(smem);
    uint32_t sB = sA + 4 * A_STAGE_B;
    uint32_t sH = sB + 8 * B_STAGE_B;

    int tid = threadIdx.x;
    int wid = tid >> 5, lane = tid & 31;
    int wm = wid >> 2, wn = wid & 3;
    int g = lane >> 2, tt = lane & 3;
    int l15 = lane & 15, lhi = (lane >> 4) << 4;

    int id = blockIdx.x;
    int b = id >> 6, slot = id & 63;
    __half* X; int L, ln;
    const __half *W1, *W2; const float *b1, *b2;
    if (slot < 8)       { X = D3; L = 1024; ln = slot * 128;        W1 = Wh + 2*65536; W2 = Wh + 3*65536; b1 = db_b1; b2 = db_b2; }
    else if (slot < 16) { X = A3; L = 1024; ln = (slot - 8) * 128;  W1 = Wh + 0*65536; W2 = Wh + 1*65536; b1 = ab_b1; b2 = ab_b2; }
    else if (slot < 32) { X = D2; L = 2048; ln = (slot - 16) * 128; W1 = Wh + 2*65536; W2 = Wh + 3*65536; b1 = db_b1; b2 = db_b2; }
    else                { X = D1; L = 4096; ln = (slot - 32) * 128; W1 = Wh + 2*65536; W2 = Wh + 3*65536; b1 = db_b1; b2 = db_b2; }
    __half* Xb = X + (size_t)b * NC * L + ln;

    float acc[4][4][4];
#pragma unroll
    for (int mt = 0; mt < 4; mt++)
#pragma unroll
        for (int nt = 0; nt < 4; nt++)
#pragma unroll
            for (int r = 0; r < 4; r++) acc[mt][nt][r] = 0.f;

    auto loadAB = [&](int c, int s) {
        const __half* wsrc = (c < 8 ? W1 : W2) + (c & 7) * 32;
#pragma unroll
        for (int q = 0; q < 2; q++) {
            int idx = tid + q * 512;
            int r = idx >> 2, u = idx & 3;
            cp16(sA + s * A_STAGE_B + r * 80 + u * 16, wsrc + r * 256 + u * 8);
        }
        if (c < 8) {
            int k = tid >> 4, u = tid & 15;
            cp16(sB + c * B_STAGE_B + k * 272 + u * 16,
                 Xb + (size_t)(c * 32 + k) * L + u * 8);
        }
    };
    auto compute = [&](int c, int s) {
        uint32_t Abase = sA + s * A_STAGE_B + (wm * 64) * 80;
        uint32_t Bbase = (c < 8) ? (sB + (uint32_t)c * B_STAGE_B)
                                 : (sH + (uint32_t)(c - 8) * 32 * 272);
#pragma unroll
        for (int kk = 0; kk < 2; kk++) {
            uint32_t a[4][4];
#pragma unroll
            for (int mt = 0; mt < 4; mt++)
                ldsm4(a[mt], Abase + (mt * 16 + l15) * 80 + kk * 32 + lhi);
            uint32_t bf[2][4];
#pragma unroll
            for (int p = 0; p < 2; p++)
                ldsm4t(bf[p], Bbase + (kk * 16 + l15) * 272 + (wn * 32 + p * 16) * 2 + lhi);
#pragma unroll
            for (int mt = 0; mt < 4; mt++)
#pragma unroll
                for (int nt = 0; nt < 4; nt++)
                    mma_f16(acc[mt][nt], a[mt], &bf[nt >> 1][(nt & 1) * 2]);
        }
    };

    loadAB(0, 0); cp_commit();
    loadAB(1, 1); cp_commit();
    loadAB(2, 2); cp_commit();

#pragma unroll 1
    for (int c = 0; c < 16; c++) {
        int s = c & 3;
        cp_wait2();
        __syncthreads();
        if (c + 3 < 16) loadAB(c + 3, (c + 3) & 3);
        cp_commit();
        compute(c, s);
        if (c == 7) {
#pragma unroll
            for (int mt = 0; mt < 4; mt++)
#pragma unroll
                for (int hh = 0; hh < 2; hh++) {
                    int m = wm * 64 + mt * 16 + g + hh * 8;
                    float bb = b1[m];
#pragma unroll
                    for (int nt = 0; nt < 4; nt++) {
                        float v0 = gelu_tanh(acc[mt][nt][hh * 2 + 0] + bb);
                        float v1 = gelu_tanh(acc[mt][nt][hh * 2 + 1] + bb);
                        __half2 h = __floats2half2_rn(v0, v1);
                        asm volatile("st.shared.b32 [%0], %1;"
                                     :: "r"(sH + m * 272 + (wn * 32 + nt * 8 + tt * 2) * 2),
                                        "r"(*(uint32_t*)&h));
                        acc[mt][nt][hh * 2 + 0] = 0.f;
                        acc[mt][nt][hh * 2 + 1] = 0.f;
                    }
                }
        }
    }

    // ---- epilogue: X(gmem) = X(smem-resident) + acc + b2 ----
#pragma unroll
    for (int mt = 0; mt < 4; mt++)
#pragma unroll
        for (int hh = 0; hh < 2; hh++) {
            int m = wm * 64 + mt * 16 + g + hh * 8;
            float bb = b2[m];
            size_t orow = (size_t)m * L;
            uint32_t xrow = sB + (uint32_t)(m >> 5) * B_STAGE_B + (uint32_t)(m & 31) * 272;
#pragma unroll
            for (int nt = 0; nt < 4; nt++) {
                int col = wn * 32 + nt * 8 + tt * 2;
                uint32_t xv;
                asm volatile("ld.shared.b32 %0, [%1];" : "=r"(xv) : "r"(xrow + col * 2));
                float2 rr = __half22float2(*(__half2*)&xv);
                float v0 = acc[mt][nt][hh * 2 + 0] + bb + rr.x;
                float v1 = acc[mt][nt][hh * 2 + 1] + bb + rr.y;
                *(__half2*)&Xb[orow + col] = __floats2half2_rn(v0, v1);
            }
        }
}

// ---------------- LayerNorm: fp16 in, fp32 out. 1024 thr, r[16] cache ----------------
// tx (0..63) owns two adjacent l (half2); ty (0..15) strides channels by 16.
__global__ __launch_bounds__(1024) void ln_kernel(const __half* __restrict__ S,
                                                  const float* __restrict__ g,
                                                  const float* __restrict__ bt,
                                                  float* __restrict__ out) {
    int b = blockIdx.y;
    int l0 = blockIdx.x * 128;
    int tx = threadIdx.x & 63;
    int ty = threadIdx.x >> 6;     // 0..15
    const __half2* Sb = (const __half2*)S;
    uint32_t r[16];
    float s0 = 0.f, s1 = 0.f, q0 = 0.f, q1 = 0.f;
#pragma unroll
    for (int q = 0; q < 16; q++) {
        int c = ty + 16 * q;
        __half2 h = Sb[(size_t)(b * NC + c) * 4096 + (l0 >> 1) + tx];
        r[q] = *(uint32_t*)&h;
        float2 f = __half22float2(h);
        s0 += f.x; s1 += f.y;
        q0 = fmaf(f.x, f.x, q0);
        q1 = fmaf(f.y, f.y, q1);
    }
    __shared__ float2 ssum[16][64], ssq[16][64];
    __shared__ float2 smu[64], srs[64];
    ssum[ty][tx] = make_float2(s0, s1);
    ssq[ty][tx] = make_float2(q0, q1);
    __syncthreads();
    if (ty == 0) {
        float2 s = ssum[0][tx], q = ssq[0][tx];
#pragma unroll
        for (int t = 1; t < 16; t++) {
            s.x += ssum[t][tx].x; s.y += ssum[t][tx].y;
            q.x += ssq[t][tx].x;  q.y += ssq[t][tx].y;
        }
        float mu0 = s.x * (1.f / NC), mu1 = s.y * (1.f / NC);
        float v0 = q.x * (1.f / NC) - mu0 * mu0;
        float v1 = q.y * (1.f / NC) - mu1 * mu1;
        smu[tx] = make_float2(mu0, mu1);
        srs[tx] = make_float2(rsqrtf(v0 + 1e-5f), rsqrtf(v1 + 1e-5f));
    }
    __syncthreads();
    float2 mu = smu[tx], rs = srs[tx];
#pragma unroll
    for (int q = 0; q < 16; q++) {
        int c = ty + 16 * q;
        __half2 h = *(__half2*)&r[q];
        float2 f = __half22float2(h);
        float gg = g[c], bbv = bt[c];
        float o0 = (f.x - mu.x) * rs.x * gg + bbv;
        float o1 = (f.y - mu.y) * rs.y * gg + bbv;
        *(float2*)&out[(size_t)(b * NC + c) * 8192 + l0 + 2 * tx] = make_float2(o0, o1);
    }
}

// ---------------- launch (single stream) ----------------
static void* sym_addr(const void* sym) {
    void* p = nullptr;
    cudaGetSymbolAddress(&p, sym);
    return p;
}

extern "C" void kernel_launch(void* const* d_in, const int* in_sizes, int n_in,
                              void* d_out, int out_size) {
    const float* x     = (const float*)d_in[0];
    const float* ab_w1 = (const float*)d_in[1];
    const float* ab_b1 = (const float*)d_in[2];
    const float* ab_w2 = (const float*)d_in[3];
    const float* ab_b2 = (const float*)d_in[4];
    const float* db_w1 = (const float*)d_in[5];
    const float* db_b1 = (const float*)d_in[6];
    const float* db_w2 = (const float*)d_in[7];
    const float* db_b2 = (const float*)d_in[8];
    const float* ln_g  = (const float*)d_in[9];
    const float* ln_b  = (const float*)d_in[10];
    float* out = (float*)d_out;

    __half* D1 = (__half*)sym_addr(g_D1);
    __half* D2 = (__half*)sym_addr(g_D2);
    __half* D3 = (__half*)sym_addr(g_D3);
    __half* A3 = (__half*)sym_addr(g_A3);
    __half* S  = (__half*)sym_addr(g_S);
    __half* Wh = (__half*)sym_addr(g_Wh);

    cudaFuncSetAttribute(resblock_all, cudaFuncAttributeMaxDynamicSharedMemorySize, RS_SMEM);
    cudaFuncSetAttribute(fused_dwt,  cudaFuncAttributeMaxDynamicSharedMemorySize, DWT_SMEM_F * 4);
    cudaFuncSetAttribute(fused_idwt, cudaFuncAttributeMaxDynamicSharedMemorySize, IDWT_SMEM_B);

    const int ROWS = NB * NC;   // 4096

    // fused forward DWT + weight conversion (64 extra blocks)
    fused_dwt<<<ROWS + 64, 512, DWT_SMEM_F * 4>>>(x, D1, D2, D3, A3,
                                                  ab_w1, ab_w2, db_w1, db_w2, Wh);

    resblock_all<<<1024, 512, RS_SMEM>>>(D3, A3, D2, D1, Wh,
                                         ab_b1, ab_b2, db_b1, db_b2);

    fused_idwt<<<ROWS, 512, IDWT_SMEM_B>>>(A3, D3, D2, D1, x, S);

    ln_kernel<<<dim3(8192 / 128, NB), 1024>>>(S, ln_g, ln_b, out);
}

// round 15
// speedup vs baseline: 1.0320x; 1.0030x over previous
#include <cuda_runtime.h>
#include <cuda_fp16.h>
#include <cstdint>
#include <math.h>

#define NB 16
#define NC 256

// ---------------- scratch (device globals: no allocs allowed) ----------------
__device__ __half g_D1[NB*NC*4096];
__device__ __half g_D2[NB*NC*2048];
__device__ __half g_D3[NB*NC*1024];
__device__ __half g_A3[NB*NC*1024];
__device__ __half g_S [NB*NC*8192];
__device__ __half g_Wh[4*NC*NC];    // fp16 weights: ab_w1, ab_w2, db_w1, db_w2

// ---------------- db4 filters ----------------
__constant__ float c_dec_lo[8] = {-0.010597401785069032f, 0.0328830116668852f, 0.030841381835560764f, -0.18703481171888114f, -0.027983769416859854f, 0.6308807679298589f, 0.7148465705529157f, 0.2303778133088965f};
__constant__ float c_dec_hi[8] = {-0.2303778133088965f, 0.7148465705529157f, -0.6308807679298589f, -0.027983769416859854f, 0.18703481171888114f, 0.030841381835560764f, -0.0328830116668852f, -0.010597401785069032f};
__constant__ float c_rec_lo[8] = {0.2303778133088965f, 0.7148465705529157f, 0.6308807679298589f, -0.027983769416859854f, -0.18703481171888114f, 0.030841381835560764f, 0.0328830116668852f, -0.010597401785069032f};
__constant__ float c_rec_hi[8] = {-0.010597401785069032f, -0.0328830116668852f, 0.030841381835560764f, 0.18703481171888114f, -0.027983769416859854f, -0.6308807679298589f, 0.7148465705529157f, -0.2303778133088965f};

// ================= helpers =================
__device__ __forceinline__ uint32_t smem_u32(const void* p) {
    uint32_t a;
    asm("{ .reg .u64 t; cvta.to.shared.u64 t, %1; cvt.u32.u64 %0, t; }" : "=r"(a) : "l"(p));
    return a;
}
__device__ __forceinline__ void cp16(uint32_t dst, const void* src) {
    asm volatile("cp.async.cg.shared.global [%0], [%1], 16;" :: "r"(dst), "l"(src));
}
__device__ __forceinline__ void cp_commit() { asm volatile("cp.async.commit_group;" ::: "memory"); }
__device__ __forceinline__ void cp_wait2()  { asm volatile("cp.async.wait_group 2;" ::: "memory"); }

__device__ __forceinline__ void mma_f16(float* c, const uint32_t* a, const uint32_t* b) {
    asm volatile("mma.sync.aligned.m16n8k16.row.col.f32.f16.f16.f32 "
                 "{%0,%1,%2,%3}, {%4,%5,%6,%7}, {%8,%9}, {%0,%1,%2,%3};"
                 : "+f"(c[0]), "+f"(c[1]), "+f"(c[2]), "+f"(c[3])
                 : "r"(a[0]), "r"(a[1]), "r"(a[2]), "r"(a[3]), "r"(b[0]), "r"(b[1]));
}
__device__ __forceinline__ void ldsm4(uint32_t* r, uint32_t addr) {
    asm volatile("ldmatrix.sync.aligned.m8n8.x4.shared.b16 {%0,%1,%2,%3}, [%4];"
                 : "=r"(r[0]), "=r"(r[1]), "=r"(r[2]), "=r"(r[3]) : "r"(addr));
}
__device__ __forceinline__ void ldsm4t(uint32_t* r, uint32_t addr) {
    asm volatile("ldmatrix.sync.aligned.m8n8.x4.trans.shared.b16 {%0,%1,%2,%3}, [%4];"
                 : "=r"(r[0]), "=r"(r[1]), "=r"(r[2]), "=r"(r[3]) : "r"(addr));
}
__device__ __forceinline__ float gelu_tanh(float x) {
    const float k0 = 0.7978845608028654f;
    const float k1 = 0.044715f;
    float x3 = x * x * x;
    float t = tanhf(k0 * (x + k1 * x3));
    return 0.5f * x * (1.f + t);
}

// ================= fused 3-level DWT + weight conversion =================
#define DWT_SMEM_F (2*4104 + 2*2056 + 2*1032)

__device__ __forceinline__ void dwt_level_h(const float* __restrict__ E, const float* __restrict__ O,
                                            int Lh, __half* __restrict__ dOut,
                                            float* EO, float* OO, __half* aOut) {
    for (int i = threadIdx.x; i < (Lh >> 1); i += 512) {
        int j = 2 * i;
        const float* e = E + 4 + j;
        const float* o = O + 4 + j;
        float em1 = e[-1], e0 = e[0], e1 = e[1], e2 = e[2], e3 = e[3];
        float om2 = o[-2], om1 = o[-1], o0 = o[0], o1 = o[1], o2 = o[2];
        float a0 = em1*c_dec_lo[1] + e0*c_dec_lo[3] + e1*c_dec_lo[5] + e2*c_dec_lo[7]
                 + om2*c_dec_lo[0] + om1*c_dec_lo[2] + o0*c_dec_lo[4] + o1*c_dec_lo[6];
        float a1 = e0*c_dec_lo[1] + e1*c_dec_lo[3] + e2*c_dec_lo[5] + e3*c_dec_lo[7]
                 + om1*c_dec_lo[0] + o0*c_dec_lo[2] + o1*c_dec_lo[4] + o2*c_dec_lo[6];
        float d0 = em1*c_dec_hi[1] + e0*c_dec_hi[3] + e1*c_dec_hi[5] + e2*c_dec_hi[7]
                 + om2*c_dec_hi[0] + om1*c_dec_hi[2] + o0*c_dec_hi[4] + o1*c_dec_hi[6];
        float d1 = e0*c_dec_hi[1] + e1*c_dec_hi[3] + e2*c_dec_hi[5] + e3*c_dec_hi[7]
                 + om1*c_dec_hi[0] + o0*c_dec_hi[2] + o1*c_dec_hi[4] + o2*c_dec_hi[6];
        *(__half2*)&dOut[j] = __floats2half2_rn(d0, d1);
        if (aOut) *(__half2*)&aOut[j] = __floats2half2_rn(a0, a1);
        else { EO[4 + i] = a0; OO[4 + i] = a1; }
    }
}

__global__ __launch_bounds__(512) void fused_dwt(const float* __restrict__ x,
                                                 __half* __restrict__ D1,
                                                 __half* __restrict__ D2,
                                                 __half* __restrict__ D3,
                                                 __half* __restrict__ A3,
                                                 const float* __restrict__ w0,
                                                 const float* __restrict__ w1,
                                                 const float* __restrict__ w2,
                                                 const float* __restrict__ w3,
                                                 __half* __restrict__ Wh) {
    int row = blockIdx.x, tid = threadIdx.x;

    if (row >= NB * NC) {
        // ---- weight conversion slice ----
        int sl = row - NB * NC;
        const float* src[4] = {w0, w1, w2, w3};
        int m = sl >> 4;
        int off = (sl & 15) * 4096;
        const float4* s4 = (const float4*)(src[m] + off);
        uint2* o4 = (uint2*)(Wh + m * 65536 + off);
#pragma unroll
        for (int q = 0; q < 2; q++) {
            float4 v = s4[tid + q * 512];
            __half2 h0 = __floats2half2_rn(v.x, v.y);
            __half2 h1 = __floats2half2_rn(v.z, v.w);
            o4[tid + q * 512] = make_uint2(*(uint32_t*)&h0, *(uint32_t*)&h1);
        }
        return;
    }

    extern __shared__ float sm[];
    float* E1 = sm;
    float* O1 = sm + 4104;
    float* E2 = sm + 8208;
    float* O2 = sm + 10264;
    float* E3 = sm + 12320;
    float* O3 = sm + 13352;

    if (tid < 48) {
        int a = tid >> 3, p = tid & 7;
        float* bases[6] = {E1, O1, E2, O2, E3, O3};
        int lens[6] = {4096, 4096, 2048, 2048, 1024, 1024};
        bases[a][p < 4 ? p : lens[a] + p] = 0.f;
    }
    const float4* x4 = (const float4*)(x + (size_t)row * 8192);
    for (int i = tid; i < 2048; i += 512) {
        float4 v = x4[i];
        *(float2*)&E1[4 + 2*i] = make_float2(v.x, v.z);
        *(float2*)&O1[4 + 2*i] = make_float2(v.y, v.w);
    }
    __syncthreads();
    dwt_level_h(E1, O1, 4096, D1 + (size_t)row * 4096, E2, O2, nullptr);
    __syncthreads();
    dwt_level_h(E2, O2, 2048, D2 + (size_t)row * 2048, E3, O3, nullptr);
    __syncthreads();
    dwt_level_h(E3, O3, 1024, D3 + (size_t)row * 1024, nullptr, nullptr, A3 + (size_t)row * 1024);
}

// ================= fused 3-level IDWT + skip, quad-processed, conflict-free =================
#define IDWT_A3H 0
#define IDWT_D3H 2080
#define IDWT_D2H 4160
#define IDWT_D1H 8288
#define IDWT_Y2  16512
#define IDWT_Y1  24736
#define IDWT_SMEM_B 41152

__global__ __launch_bounds__(512) void fused_idwt(const __half* __restrict__ A3v,
                                                  const __half* __restrict__ D3v,
                                                  const __half* __restrict__ D2v,
                                                  const __half* __restrict__ D1v,
                                                  const float* __restrict__ x,
                                                  __half* __restrict__ S) {
    extern __shared__ char smc[];
    __half* A3h = (__half*)(smc + IDWT_A3H);
    __half* D3h = (__half*)(smc + IDWT_D3H);
    __half* D2h = (__half*)(smc + IDWT_D2H);
    __half* D1h = (__half*)(smc + IDWT_D1H);
    float*  Y2  = (float*)(smc + IDWT_Y2);
    float*  Y1  = (float*)(smc + IDWT_Y1);
    int row = blockIdx.x, tid = threadIdx.x;

    if (tid < 8) {
        __half* hb[4] = {A3h, D3h, D2h, D1h};
        int hl[4] = {1024, 1024, 2048, 4096};
        int a = tid >> 1, e = tid & 1;
        uint4 z = make_uint4(0, 0, 0, 0);
        *(uint4*)&hb[a][e ? 8 + hl[a] : 0] = z;
    } else if (tid < 12) {
        float* fb[2] = {Y2, Y1};
        int fl[2] = {2048, 4096};
        int a = (tid - 8) >> 1, e = tid & 1;
        *(float4*)&fb[a][e ? 4 + fl[a] : 0] = make_float4(0.f, 0.f, 0.f, 0.f);
    }
    {
        const uint4* a3 = (const uint4*)(A3v + (size_t)row * 1024);
        const uint4* d3 = (const uint4*)(D3v + (size_t)row * 1024);
        const uint4* d2 = (const uint4*)(D2v + (size_t)row * 2048);
        const uint4* d1 = (const uint4*)(D1v + (size_t)row * 4096);
        if (tid < 128)       *(uint4*)&A3h[8 + 8 * tid] = a3[tid];
        else if (tid < 256)  *(uint4*)&D3h[8 + 8 * (tid - 128)] = d3[tid - 128];
        else                 *(uint4*)&D2h[8 + 8 * (tid - 256)] = d2[tid - 256];
        *(uint4*)&D1h[8 + 8 * tid] = d1[tid];
    }
    __syncthreads();

    {
        int i = tid;
        float2 am = __half22float2(*(const __half2*)&A3h[6 + 2*i]);
        float2 ac = __half22float2(*(const __half2*)&A3h[8 + 2*i]);
        float2 ap = __half22float2(*(const __half2*)&A3h[10 + 2*i]);
        float2 dm = __half22float2(*(const __half2*)&D3h[6 + 2*i]);
        float2 dc = __half22float2(*(const __half2*)&D3h[8 + 2*i]);
        float2 dp = __half22float2(*(const __half2*)&D3h[10 + 2*i]);
        float y0 = am.x*c_rec_lo[7] + am.y*c_rec_lo[5] + ac.x*c_rec_lo[3] + ac.y*c_rec_lo[1]
                 + dm.x*c_rec_hi[7] + dm.y*c_rec_hi[5] + dc.x*c_rec_hi[3] + dc.y*c_rec_hi[1];
        float y1 = am.y*c_rec_lo[6] + ac.x*c_rec_lo[4] + ac.y*c_rec_lo[2] + ap.x*c_rec_lo[0]
                 + dm.y*c_rec_hi[6] + dc.x*c_rec_hi[4] + dc.y*c_rec_hi[2] + dp.x*c_rec_hi[0];
        float y2 = am.y*c_rec_lo[7] + ac.x*c_rec_lo[5] + ac.y*c_rec_lo[3] + ap.x*c_rec_lo[1]
                 + dm.y*c_rec_hi[7] + dc.x*c_rec_hi[5] + dc.y*c_rec_hi[3] + dp.x*c_rec_hi[1];
        float y3 = ac.x*c_rec_lo[6] + ac.y*c_rec_lo[4] + ap.x*c_rec_lo[2] + ap.y*c_rec_lo[0]
                 + dc.x*c_rec_hi[6] + dc.y*c_rec_hi[4] + dp.x*c_rec_hi[2] + dp.y*c_rec_hi[0];
        *(float4*)&Y2[4 + 4*i] = make_float4(y0, y1, y2, y3);
    }
    __syncthreads();

#pragma unroll
    for (int q = 0; q < 2; q++) {
        int i = tid + q * 512;
        float2 am = *(const float2*)&Y2[2 + 2*i];
        float2 ac = *(const float2*)&Y2[4 + 2*i];
        float2 ap = *(const float2*)&Y2[6 + 2*i];
        float2 dm = __half22float2(*(const __half2*)&D2h[6 + 2*i]);
        float2 dc = __half22float2(*(const __half2*)&D2h[8 + 2*i]);
        float2 dp = __half22float2(*(const __half2*)&D2h[10 + 2*i]);
        float y0 = am.x*c_rec_lo[7] + am.y*c_rec_lo[5] + ac.x*c_rec_lo[3] + ac.y*c_rec_lo[1]
                 + dm.x*c_rec_hi[7] + dm.y*c_rec_hi[5] + dc.x*c_rec_hi[3] + dc.y*c_rec_hi[1];
        float y1 = am.y*c_rec_lo[6] + ac.x*c_rec_lo[4] + ac.y*c_rec_lo[2] + ap.x*c_rec_lo[0]
                 + dm.y*c_rec_hi[6] + dc.x*c_rec_hi[4] + dc.y*c_rec_hi[2] + dp.x*c_rec_hi[0];
        float y2 = am.y*c_rec_lo[7] + ac.x*c_rec_lo[5] + ac.y*c_rec_lo[3] + ap.x*c_rec_lo[1]
                 + dm.y*c_rec_hi[7] + dc.x*c_rec_hi[5] + dc.y*c_rec_hi[3] + dp.x*c_rec_hi[1];
        float y3 = ac.x*c_rec_lo[6] + ac.y*c_rec_lo[4] + ap.x*c_rec_lo[2] + ap.y*c_rec_lo[0]
                 + dc.x*c_rec_hi[6] + dc.y*c_rec_hi[4] + dp.x*c_rec_hi[2] + dp.y*c_rec_hi[0];
        *(float4*)&Y1[4 + 4*i] = make_float4(y0, y1, y2, y3);
    }
    __syncthreads();

    const float* xr = x + (size_t)row * 8192;
    __half* Sr = S + (size_t)row * 8192;
#pragma unroll
    for (int q = 0; q < 4; q++) {
        int i = tid + q * 512;
        float2 am = *(const float2*)&Y1[2 + 2*i];
        float2 ac = *(const float2*)&Y1[4 + 2*i];
        float2 ap = *(const float2*)&Y1[6 + 2*i];
        float2 dm = __half22float2(*(const __half2*)&D1h[6 + 2*i]);
        float2 dc = __half22float2(*(const __half2*)&D1h[8 + 2*i]);
        float2 dp = __half22float2(*(const __half2*)&D1h[10 + 2*i]);
        float y0 = am.x*c_rec_lo[7] + am.y*c_rec_lo[5] + ac.x*c_rec_lo[3] + ac.y*c_rec_lo[1]
                 + dm.x*c_rec_hi[7] + dm.y*c_rec_hi[5] + dc.x*c_rec_hi[3] + dc.y*c_rec_hi[1];
        float y1 = am.y*c_rec_lo[6] + ac.x*c_rec_lo[4] + ac.y*c_rec_lo[2] + ap.x*c_rec_lo[0]
                 + dm.y*c_rec_hi[6] + dc.x*c_rec_hi[4] + dc.y*c_rec_hi[2] + dp.x*c_rec_hi[0];
        float y2 = am.y*c_rec_lo[7] + ac.x*c_rec_lo[5] + ac.y*c_rec_lo[3] + ap.x*c_rec_lo[1]
                 + dm.y*c_rec_hi[7] + dc.x*c_rec_hi[5] + dc.y*c_rec_hi[3] + dp.x*c_rec_hi[1];
        float y3 = ac.x*c_rec_lo[6] + ac.y*c_rec_lo[4] + ap.x*c_rec_lo[2] + ap.y*c_rec_lo[0]
                 + dc.x*c_rec_hi[6] + dc.y*c_rec_hi[4] + dp.x*c_rec_hi[2] + dp.y*c_rec_hi[0];
        float4 xv = *(const float4*)&xr[4*i];
        __half2 h0 = __floats2half2_rn(y0 + xv.x, y1 + xv.y);
        __half2 h1 = __floats2half2_rn(y2 + xv.z, y3 + xv.w);
        uint2 pk = make_uint2(*(uint32_t*)&h0, *(uint32_t*)&h1);
        *(uint2*)&Sr[4*i] = pk;
    }
}

// ================= combined fused res blocks (round-8 structure, best measured) =================
#define A_STAGE_B (256*80)      // 20480
#define B_STAGE_B (32*272)      // 8704
#define H_BYTES   (256*272)     // 69632
#define RS_SMEM   (4*A_STAGE_B + 8*B_STAGE_B + H_BYTES)   // 221184

__global__ __launch_bounds__(512, 1) void resblock_all(
        __half* __restrict__ D3, __half* __restrict__ A3,
        __half* __restrict__ D2, __half* __restrict__ D1,
        const __half* __restrict__ Wh,
        const float* __restrict__ ab_b1, const float* __restrict__ ab_b2,
        const float* __restrict__ db_b1, const float* __restrict__ db_b2) {
    extern __shared__ char smem[];
    uint32_t sA = smem_u32(smem);
    uint32_t sB = sA + 4 * A_STAGE_B;
    uint32_t sH = sB + 8 * B_STAGE_B;

    int tid = threadIdx.x;
    int wid = tid >> 5, lane = tid & 31;
    int wm = wid >> 2, wn = wid & 3;
    int g = lane >> 2, tt = lane & 3;
    int l15 = lane & 15, lhi = (lane >> 4) << 4;

    int id = blockIdx.x;
    int b = id >> 6, slot = id & 63;
    __half* X; int L, ln;
    const __half *W1, *W2; const float *b1, *b2;
    if (slot < 8)       { X = D3; L = 1024; ln = slot * 128;        W1 = Wh + 2*65536; W2 = Wh + 3*65536; b1 = db_b1; b2 = db_b2; }
    else if (slot < 16) { X = A3; L = 1024; ln = (slot - 8) * 128;  W1 = Wh + 0*65536; W2 = Wh + 1*65536; b1 = ab_b1; b2 = ab_b2; }
    else if (slot < 32) { X = D2; L = 2048; ln = (slot - 16) * 128; W1 = Wh + 2*65536; W2 = Wh + 3*65536; b1 = db_b1; b2 = db_b2; }
    else                { X = D1; L = 4096; ln = (slot - 32) * 128; W1 = Wh + 2*65536; W2 = Wh + 3*65536; b1 = db_b1; b2 = db_b2; }
    __half* Xb = X + (size_t)b * NC * L + ln;

    float acc[4][4][4];
#pragma unroll
    for (int mt = 0; mt < 4; mt++)
#pragma unroll
        for (int nt = 0; nt < 4; nt++)
#pragma unroll
            for (int r = 0; r < 4; r++) acc[mt][nt][r] = 0.f;

    auto loadAB = [&](int c, int s) {
        const __half* wsrc = (c < 8 ? W1 : W2) + (c & 7) * 32;
#pragma unroll
        for (int q = 0; q < 2; q++) {
            int idx = tid + q * 512;
            int r = idx >> 2, u = idx & 3;
            cp16(sA + s * A_STAGE_B + r * 80 + u * 16, wsrc + r * 256 + u * 8);
        }
        if (c < 8) {
            int k = tid >> 4, u = tid & 15;
            cp16(sB + c * B_STAGE_B + k * 272 + u * 16,
                 Xb + (size_t)(c * 32 + k) * L + u * 8);
        }
    };
    auto compute = [&](int c, int s) {
        uint32_t Abase = sA + s * A_STAGE_B + (wm * 64) * 80;
        uint32_t Bbase = (c < 8) ? (sB + (uint32_t)c * B_STAGE_B)
                                 : (sH + (uint32_t)(c - 8) * 32 * 272);
#pragma unroll
        for (int kk = 0; kk < 2; kk++) {
            uint32_t a[4][4];
#pragma unroll
            for (int mt = 0; mt < 4; mt++)
                ldsm4(a[mt], Abase + (mt * 16 + l15) * 80 + kk * 32 + lhi);
            uint32_t bf[2][4];
#pragma unroll
            for (int p = 0; p < 2; p++)
                ldsm4t(bf[p], Bbase + (kk * 16 + l15) * 272 + (wn * 32 + p * 16) * 2 + lhi);
#pragma unroll
            for (int mt = 0; mt < 4; mt++)
#pragma unroll
                for (int nt = 0; nt < 4; nt++)
                    mma_f16(acc[mt][nt], a[mt], &bf[nt >> 1][(nt & 1) * 2]);
        }
    };

    loadAB(0, 0); cp_commit();
    loadAB(1, 1); cp_commit();
    loadAB(2, 2); cp_commit();

#pragma unroll 1
    for (int c = 0; c < 16; c++) {
        int s = c & 3;
        cp_wait2();
        __syncthreads();
        if (c + 3 < 16) loadAB(c + 3, (c + 3) & 3);
        cp_commit();
        compute(c, s);
        if (c == 7) {
#pragma unroll
            for (int mt = 0; mt < 4; mt++)
#pragma unroll
                for (int hh = 0; hh < 2; hh++) {
                    int m = wm * 64 + mt * 16 + g + hh * 8;
                    float bb = b1[m];
#pragma unroll
                    for (int nt = 0; nt < 4; nt++) {
                        float v0 = gelu_tanh(acc[mt][nt][hh * 2 + 0] + bb);
                        float v1 = gelu_tanh(acc[mt][nt][hh * 2 + 1] + bb);
                        __half2 h = __floats2half2_rn(v0, v1);
                        asm volatile("st.shared.b32 [%0], %1;"
                                     :: "r"(sH + m * 272 + (wn * 32 + nt * 8 + tt * 2) * 2),
                                        "r"(*(uint32_t*)&h));
                        acc[mt][nt][hh * 2 + 0] = 0.f;
                        acc[mt][nt][hh * 2 + 1] = 0.f;
                    }
                }
        }
    }

    // ---- epilogue: X(gmem) = X(smem-resident) + acc + b2 ----
#pragma unroll
    for (int mt = 0; mt < 4; mt++)
#pragma unroll
        for (int hh = 0; hh < 2; hh++) {
            int m = wm * 64 + mt * 16 + g + hh * 8;
            float bb = b2[m];
            size_t orow = (size_t)m * L;
            uint32_t xrow = sB + (uint32_t)(m >> 5) * B_STAGE_B + (uint32_t)(m & 31) * 272;
#pragma unroll
            for (int nt = 0; nt < 4; nt++) {
                int col = wn * 32 + nt * 8 + tt * 2;
                uint32_t xv;
                asm volatile("ld.shared.b32 %0, [%1];" : "=r"(xv) : "r"(xrow + col * 2));
                float2 rr = __half22float2(*(__half2*)&xv);
                float v0 = acc[mt][nt][hh * 2 + 0] + bb + rr.x;
                float v1 = acc[mt][nt][hh * 2 + 1] + bb + rr.y;
                *(__half2*)&Xb[orow + col] = __floats2half2_rn(v0, v1);
            }
        }
}

// ---------------- LayerNorm: fp16 in (uint2 loads), fp32 out (float4 stores) ----------------
// tx (0..31) owns 4 adjacent l; ty (0..31) strides channels by 32; r[8] channel cache.
__global__ __launch_bounds__(1024) void ln_kernel(const __half* __restrict__ S,
                                                  const float* __restrict__ g,
                                                  const float* __restrict__ bt,
                                                  float* __restrict__ out) {
    int b = blockIdx.y;
    int l0 = blockIdx.x * 128;
    int tx = threadIdx.x & 31;
    int ty = threadIdx.x >> 5;     // 0..31
    const uint2* Sb = (const uint2*)S;   // 4 halves per elem
    uint2 r[8];
    float s0 = 0.f, s1 = 0.f, s2 = 0.f, s3 = 0.f;
    float q0 = 0.f, q1 = 0.f, q2 = 0.f, q3 = 0.f;
#pragma unroll
    for (int q = 0; q < 8; q++) {
        int c = ty + 32 * q;
        uint2 h = Sb[(size_t)(b * NC + c) * 2048 + (l0 >> 2) + tx];
        r[q] = h;
        float2 f0 = __half22float2(*(__half2*)&h.x);
        float2 f1 = __half22float2(*(__half2*)&h.y);
        s0 += f0.x; s1 += f0.y; s2 += f1.x; s3 += f1.y;
        q0 = fmaf(f0.x, f0.x, q0);
        q1 = fmaf(f0.y, f0.y, q1);
        q2 = fmaf(f1.x, f1.x, q2);
        q3 = fmaf(f1.y, f1.y, q3);
    }
    __shared__ float4 ssum[32][32], ssq[32][32];
    __shared__ float4 smu[32], srs[32];
    ssum[ty][tx] = make_float4(s0, s1, s2, s3);
    ssq[ty][tx] = make_float4(q0, q1, q2, q3);
    __syncthreads();
    if (ty == 0) {
        float4 s = ssum[0][tx], q = ssq[0][tx];
#pragma unroll
        for (int t = 1; t < 32; t++) {
            float4 a = ssum[t][tx], z = ssq[t][tx];
            s.x += a.x; s.y += a.y; s.z += a.z; s.w += a.w;
            q.x += z.x; q.y += z.y; q.z += z.z; q.w += z.w;
        }
        float4 mu = make_float4(s.x * (1.f / NC), s.y * (1.f / NC),
                                s.z * (1.f / NC), s.w * (1.f / NC));
        smu[tx] = mu;
        srs[tx] = make_float4(rsqrtf(q.x * (1.f / NC) - mu.x * mu.x + 1e-5f),
                              rsqrtf(q.y * (1.f / NC) - mu.y * mu.y + 1e-5f),
                              rsqrtf(q.z * (1.f / NC) - mu.z * mu.z + 1e-5f),
                              rsqrtf(q.w * (1.f / NC) - mu.w * mu.w + 1e-5f));
    }
    __syncthreads();
    float4 mu = smu[tx], rs = srs[tx];
#pragma unroll
    for (int q = 0; q < 8; q++) {
        int c = ty + 32 * q;
        float2 f0 = __half22float2(*(__half2*)&r[q].x);
        float2 f1 = __half22float2(*(__half2*)&r[q].y);
        float gg = g[c], bbv = bt[c];
        float4 o;
        o.x = (f0.x - mu.x) * rs.x * gg + bbv;
        o.y = (f0.y - mu.y) * rs.y * gg + bbv;
        o.z = (f1.x - mu.z) * rs.z * gg + bbv;
        o.w = (f1.y - mu.w) * rs.w * gg + bbv;
        *(float4*)&out[(size_t)(b * NC + c) * 8192 + l0 + 4 * tx] = o;
    }
}

// ---------------- launch (single stream) ----------------
static void* sym_addr(const void* sym) {
    void* p = nullptr;
    cudaGetSymbolAddress(&p, sym);
    return p;
}

extern "C" void kernel_launch(void* const* d_in, const int* in_sizes, int n_in,
                              void* d_out, int out_size) {
    const float* x     = (const float*)d_in[0];
    const float* ab_w1 = (const float*)d_in[1];
    const float* ab_b1 = (const float*)d_in[2];
    const float* ab_w2 = (const float*)d_in[3];
    const float* ab_b2 = (const float*)d_in[4];
    const float* db_w1 = (const float*)d_in[5];
    const float* db_b1 = (const float*)d_in[6];
    const float* db_w2 = (const float*)d_in[7];
    const float* db_b2 = (const float*)d_in[8];
    const float* ln_g  = (const float*)d_in[9];
    const float* ln_b  = (const float*)d_in[10];
    float* out = (float*)d_out;

    __half* D1 = (__half*)sym_addr(g_D1);
    __half* D2 = (__half*)sym_addr(g_D2);
    __half* D3 = (__half*)sym_addr(g_D3);
    __half* A3 = (__half*)sym_addr(g_A3);
    __half* S  = (__half*)sym_addr(g_S);
    __half* Wh = (__half*)sym_addr(g_Wh);

    cudaFuncSetAttribute(resblock_all, cudaFuncAttributeMaxDynamicSharedMemorySize, RS_SMEM);
    cudaFuncSetAttribute(fused_dwt,  cudaFuncAttributeMaxDynamicSharedMemorySize, DWT_SMEM_F * 4);
    cudaFuncSetAttribute(fused_idwt, cudaFuncAttributeMaxDynamicSharedMemorySize, IDWT_SMEM_B);

    const int ROWS = NB * NC;   // 4096

    // fused forward DWT + weight conversion (64 extra blocks)
    fused_dwt<<<ROWS + 64, 512, DWT_SMEM_F * 4>>>(x, D1, D2, D3, A3,
                                                  ab_w1, ab_w2, db_w1, db_w2, Wh);

    resblock_all<<<1024, 512, RS_SMEM>>>(D3, A3, D2, D1, Wh,
                                         ab_b1, ab_b2, db_b1, db_b2);

    fused_idwt<<<ROWS, 512, IDWT_SMEM_B>>>(A3, D3, D2, D1, x, S);

    ln_kernel<<<dim3(8192 / 128, NB), 1024>>>(S, ln_g, ln_b, out);
}